// round 1
// baseline (speedup 1.0000x reference)
#include <cuda_runtime.h>

// Problem constants
#define S_LEN    2048
#define DMODEL   1024
#define NHEADS   16
#define DK       64
#define BATCH    2
#define M_TOTAL  (BATCH * S_LEN)   // 4096

// Scratch (allocation-free rule: __device__ globals)
__device__ float g_q[BATCH * NHEADS * S_LEN * DK];     // (B,H,S,dk)
__device__ float g_k[BATCH * NHEADS * S_LEN * DK];
__device__ float g_v[BATCH * NHEADS * S_LEN * DK];
__device__ float g_att[BATCH * S_LEN * DMODEL];        // (B,S,D)

// ---------------------------------------------------------------------------
// GEMM: C[m][n] = sum_k A[m][k] * W[n][k]   (A: MxK row-major, W: NxK row-major)
// Tiling: 128x128x8, 256 threads, 8x8 per-thread micro-tile (2x2 blocks of 4x4).
// scatter=1 -> write into (B,H,S,dk) layout; scatter=0 -> plain MxN row-major.
// blockIdx.z selects (W,C) pair (fused QKV).
// ---------------------------------------------------------------------------
__global__ __launch_bounds__(256) void gemm_nt_kernel(
    const float* __restrict__ A,
    const float* __restrict__ W0, const float* __restrict__ W1, const float* __restrict__ W2,
    float* __restrict__ C0, float* __restrict__ C1, float* __restrict__ C2,
    int scatter)
{
    const float* __restrict__ W = (blockIdx.z == 0) ? W0 : (blockIdx.z == 1) ? W1 : W2;
    float* __restrict__ C       = (blockIdx.z == 0) ? C0 : (blockIdx.z == 1) ? C1 : C2;

    __shared__ float As[8][132];   // transposed stage: As[k][m_local]
    __shared__ float Bs[8][132];   // transposed stage: Bs[k][n_local]

    const int tid   = threadIdx.x;
    const int tx    = tid & 15;          // 0..15 -> cols
    const int ty    = tid >> 4;          // 0..15 -> rows
    const int nBase = blockIdx.x * 128;
    const int mBase = blockIdx.y * 128;

    const int loadRow = tid >> 1;        // 0..127
    const int loadK   = (tid & 1) * 4;   // 0 or 4

    float acc[8][8];
#pragma unroll
    for (int i = 0; i < 8; i++)
#pragma unroll
        for (int j = 0; j < 8; j++) acc[i][j] = 0.0f;

    const float* Aptr = A + (mBase + loadRow) * DMODEL + loadK;
    const float* Wptr = W + (nBase + loadRow) * DMODEL + loadK;

    for (int kt = 0; kt < DMODEL / 8; kt++) {
        float4 a  = *(const float4*)(Aptr + kt * 8);
        float4 bv = *(const float4*)(Wptr + kt * 8);

        __syncthreads();
        As[loadK + 0][loadRow] = a.x;  As[loadK + 1][loadRow] = a.y;
        As[loadK + 2][loadRow] = a.z;  As[loadK + 3][loadRow] = a.w;
        Bs[loadK + 0][loadRow] = bv.x; Bs[loadK + 1][loadRow] = bv.y;
        Bs[loadK + 2][loadRow] = bv.z; Bs[loadK + 3][loadRow] = bv.w;
        __syncthreads();

#pragma unroll
        for (int kk = 0; kk < 8; kk++) {
            float4 a0 = *(const float4*)&As[kk][ty * 4];
            float4 a1 = *(const float4*)&As[kk][64 + ty * 4];
            float4 b0 = *(const float4*)&Bs[kk][tx * 4];
            float4 b1 = *(const float4*)&Bs[kk][64 + tx * 4];
            float ar[8] = {a0.x, a0.y, a0.z, a0.w, a1.x, a1.y, a1.z, a1.w};
            float br[8] = {b0.x, b0.y, b0.z, b0.w, b1.x, b1.y, b1.z, b1.w};
#pragma unroll
            for (int i = 0; i < 8; i++)
#pragma unroll
                for (int j = 0; j < 8; j++)
                    acc[i][j] = fmaf(ar[i], br[j], acc[i][j]);
        }
    }

    // Epilogue
#pragma unroll
    for (int rg = 0; rg < 2; rg++) {
#pragma unroll
        for (int i = 0; i < 4; i++) {
            const int m = mBase + rg * 64 + ty * 4 + i;
#pragma unroll
            for (int cg = 0; cg < 2; cg++) {
                const int n0 = nBase + cg * 64 + tx * 4;
                float4 val;
                val.x = acc[rg * 4 + i][cg * 4 + 0];
                val.y = acc[rg * 4 + i][cg * 4 + 1];
                val.z = acc[rg * 4 + i][cg * 4 + 2];
                val.w = acc[rg * 4 + i][cg * 4 + 3];
                if (scatter) {
                    const int b = m >> 11;          // m / 2048
                    const int s = m & 2047;
                    const int head = n0 >> 6;       // n0 / 64
                    const int d = n0 & 63;
                    *(float4*)&C[(((b << 4) + head) * S_LEN + s) * DK + d] = val;
                } else {
                    *(float4*)&C[m * DMODEL + n0] = val;
                }
            }
        }
    }
}

// ---------------------------------------------------------------------------
// Flash attention (fp32). grid = (32 q-tiles, 32 b*h). block = 256.
// Q tile 64x64 resident; K/V streamed in 64-row tiles; online softmax.
// Thread map: ty=row group (4 rows), tx: score cols {tx+16*jj}, O cols {4*tx+j}.
// ---------------------------------------------------------------------------
#define TPAD 68
#define ATTN_SMEM (4 * 64 * TPAD * (int)sizeof(float))

__global__ __launch_bounds__(256) void attn_kernel(
    const float* __restrict__ Q, const float* __restrict__ K,
    const float* __restrict__ V, float* __restrict__ Oatt)
{
    extern __shared__ float sm[];
    float* sQ = sm;
    float* sK = sm + 64 * TPAD;
    float* sV = sm + 2 * 64 * TPAD;
    float* sP = sm + 3 * 64 * TPAD;

    const int tid = threadIdx.x;
    const int tx  = tid & 15;
    const int ty  = tid >> 4;
    const int qt  = blockIdx.x;
    const int bh  = blockIdx.y;
    const int b   = bh >> 4;
    const int h   = bh & 15;

    // Load Q tile (coalesced float4, swizzle into padded smem)
    const float* Qg = Q + (bh * S_LEN + qt * 64) * DK;
#pragma unroll
    for (int p = 0; p < 4; p++) {
        int lin = (p * 256 + tid) * 4;
        int r = lin >> 6, c = lin & 63;
        *(float4*)&sQ[r * TPAD + c] = *(const float4*)&Qg[lin];
    }

    float acc[4][4];
    float mrow[4], lrow[4];
#pragma unroll
    for (int i = 0; i < 4; i++) {
        mrow[i] = -1e30f; lrow[i] = 0.0f;
#pragma unroll
        for (int j = 0; j < 4; j++) acc[i][j] = 0.0f;
    }

    for (int kt = 0; kt < S_LEN / 64; kt++) {
        __syncthreads();   // protect sK/sV/sP overwrite vs previous iteration reads
        const float* Kg = K + (bh * S_LEN + kt * 64) * DK;
        const float* Vg = V + (bh * S_LEN + kt * 64) * DK;
#pragma unroll
        for (int p = 0; p < 4; p++) {
            int lin = (p * 256 + tid) * 4;
            int r = lin >> 6, c = lin & 63;
            *(float4*)&sK[r * TPAD + c] = *(const float4*)&Kg[lin];
            *(float4*)&sV[r * TPAD + c] = *(const float4*)&Vg[lin];
        }
        __syncthreads();

        // Scores: s[i][jj] = Q[row 4ty+i] . K[col tx+16jj]
        float s[4][4];
#pragma unroll
        for (int i = 0; i < 4; i++)
#pragma unroll
            for (int j = 0; j < 4; j++) s[i][j] = 0.0f;

#pragma unroll 4
        for (int d4 = 0; d4 < 16; d4++) {
            float4 q[4], kk4[4];
#pragma unroll
            for (int i = 0; i < 4; i++)
                q[i] = *(const float4*)&sQ[(ty * 4 + i) * TPAD + d4 * 4];
#pragma unroll
            for (int jj = 0; jj < 4; jj++)
                kk4[jj] = *(const float4*)&sK[(tx + jj * 16) * TPAD + d4 * 4];
#pragma unroll
            for (int i = 0; i < 4; i++)
#pragma unroll
                for (int jj = 0; jj < 4; jj++) {
                    s[i][jj] = fmaf(q[i].x, kk4[jj].x, s[i][jj]);
                    s[i][jj] = fmaf(q[i].y, kk4[jj].y, s[i][jj]);
                    s[i][jj] = fmaf(q[i].z, kk4[jj].z, s[i][jj]);
                    s[i][jj] = fmaf(q[i].w, kk4[jj].w, s[i][jj]);
                }
        }

        // Online softmax per row
#pragma unroll
        for (int i = 0; i < 4; i++) {
#pragma unroll
            for (int jj = 0; jj < 4; jj++) s[i][jj] *= 0.125f;  // 1/sqrt(64)
            float mloc = fmaxf(fmaxf(s[i][0], s[i][1]), fmaxf(s[i][2], s[i][3]));
#pragma unroll
            for (int off = 8; off >= 1; off >>= 1)
                mloc = fmaxf(mloc, __shfl_xor_sync(0xffffffffu, mloc, off, 16));
            float mnew = fmaxf(mrow[i], mloc);
            float alpha = __expf(mrow[i] - mnew);
            mrow[i] = mnew;
            float lloc = 0.0f;
#pragma unroll
            for (int jj = 0; jj < 4; jj++) {
                float pv = __expf(s[i][jj] - mnew);
                s[i][jj] = pv;
                lloc += pv;
            }
#pragma unroll
            for (int off = 8; off >= 1; off >>= 1)
                lloc += __shfl_xor_sync(0xffffffffu, lloc, off, 16);
            lrow[i] = lrow[i] * alpha + lloc;
#pragma unroll
            for (int j = 0; j < 4; j++) acc[i][j] *= alpha;
#pragma unroll
            for (int jj = 0; jj < 4; jj++)
                sP[(ty * 4 + i) * TPAD + tx + jj * 16] = s[i][jj];
        }
        __syncthreads();

        // O += P @ V : acc[i][j] over d-cols {4tx+j}
#pragma unroll 4
        for (int jc = 0; jc < 16; jc++) {
            float pr[4][4];
            float4 vr[4];
#pragma unroll
            for (int i = 0; i < 4; i++) {
                float4 t = *(const float4*)&sP[(ty * 4 + i) * TPAD + jc * 4];
                pr[i][0] = t.x; pr[i][1] = t.y; pr[i][2] = t.z; pr[i][3] = t.w;
            }
#pragma unroll
            for (int u = 0; u < 4; u++)
                vr[u] = *(const float4*)&sV[(jc * 4 + u) * TPAD + tx * 4];
#pragma unroll
            for (int i = 0; i < 4; i++) {
#pragma unroll
                for (int u = 0; u < 4; u++) {
                    acc[i][0] = fmaf(pr[i][u], vr[u].x, acc[i][0]);
                    acc[i][1] = fmaf(pr[i][u], vr[u].y, acc[i][1]);
                    acc[i][2] = fmaf(pr[i][u], vr[u].z, acc[i][2]);
                    acc[i][3] = fmaf(pr[i][u], vr[u].w, acc[i][3]);
                }
            }
        }
    }

    // Normalize + write (B,S,D)
#pragma unroll
    for (int i = 0; i < 4; i++) {
        float inv = 1.0f / lrow[i];
        float4 o;
        o.x = acc[i][0] * inv; o.y = acc[i][1] * inv;
        o.z = acc[i][2] * inv; o.w = acc[i][3] * inv;
        const int row = qt * 64 + ty * 4 + i;
        *(float4*)&Oatt[(b * S_LEN + row) * DMODEL + h * DK + tx * 4] = o;
    }
}

// ---------------------------------------------------------------------------
extern "C" void kernel_launch(void* const* d_in, const int* in_sizes, int n_in,
                              void* d_out, int out_size)
{
    const float* x  = (const float*)d_in[0];
    const float* Wq = (const float*)d_in[1];
    const float* Wk = (const float*)d_in[2];
    const float* Wv = (const float*)d_in[3];
    const float* Wo = (const float*)d_in[4];
    float* out = (float*)d_out;

    float *qp, *kp, *vp, *attp;
    cudaGetSymbolAddress((void**)&qp,  g_q);
    cudaGetSymbolAddress((void**)&kp,  g_k);
    cudaGetSymbolAddress((void**)&vp,  g_v);
    cudaGetSymbolAddress((void**)&attp, g_att);

    // 1) Fused QKV projections: x(4096x1024) @ W^T, scatter to (B,H,S,dk)
    dim3 gQKV(DMODEL / 128, M_TOTAL / 128, 3);
    gemm_nt_kernel<<<gQKV, 256>>>(x, Wq, Wk, Wv, qp, kp, vp, 1);

    // 2) Flash attention -> (B,S,D)
    cudaFuncSetAttribute(attn_kernel, cudaFuncAttributeMaxDynamicSharedMemorySize,
                         ATTN_SMEM);
    dim3 gA(S_LEN / 64, BATCH * NHEADS);
    attn_kernel<<<gA, 256, ATTN_SMEM>>>(qp, kp, vp, attp);

    // 3) Output projection -> d_out
    dim3 gO(DMODEL / 128, M_TOTAL / 128, 1);
    gemm_nt_kernel<<<gO, 256>>>(attp, Wo, Wo, Wo, out, out, out, 0);
}

// round 3
// speedup vs baseline: 4.2118x; 4.2118x over previous
#include <cuda_runtime.h>
#include <cstdint>

// Problem constants
#define S_LEN    2048
#define DMODEL   1024
#define NHEADS   16
#define DK       64
#define BATCH    2
#define M_TOTAL  (BATCH * S_LEN)   // 4096

// Scratch (allocation-free rule: __device__ globals)
__device__ float g_q[BATCH * NHEADS * S_LEN * DK];     // (B,H,S,dk) tf32-rounded
__device__ float g_k[BATCH * NHEADS * S_LEN * DK];
__device__ float g_v[BATCH * NHEADS * S_LEN * DK];
__device__ float g_att[BATCH * S_LEN * DMODEL];        // (B,S,D) tf32-rounded
__device__ float g_round[8 * 1024 * 1024];             // rounded x + 4 weights

// ---------------------------------------------------------------------------
// Helpers
// ---------------------------------------------------------------------------
__device__ __forceinline__ uint32_t smem_u32(const void* p) {
    uint32_t a;
    asm("{ .reg .u64 t; cvta.to.shared.u64 t, %1; cvt.u32.u64 %0, t; }"
        : "=r"(a) : "l"(p));
    return a;
}

__device__ __forceinline__ void cp_async16(uint32_t s, const void* g) {
    asm volatile("cp.async.cg.shared.global [%0], [%1], 16;" :: "r"(s), "l"(g));
}
#define CP_COMMIT() asm volatile("cp.async.commit_group;" ::: "memory")
#define CP_WAIT(n)  asm volatile("cp.async.wait_group %0;" :: "n"(n) : "memory")

__device__ __forceinline__ float round_tf32(float v) {
    uint32_t u;
    asm("cvt.rna.tf32.f32 %0, %1;" : "=r"(u) : "f"(v));
    return __uint_as_float(u);
}

// D(16x8) += A(16x8,row) * B(8x8,col)  -- tf32, fp32 accum
__device__ __forceinline__ void mma_tf32(float* d,
                                         uint32_t a0, uint32_t a1, uint32_t a2, uint32_t a3,
                                         uint32_t b0, uint32_t b1) {
    asm volatile(
        "mma.sync.aligned.m16n8k8.row.col.f32.tf32.tf32.f32 "
        "{%0,%1,%2,%3}, {%4,%5,%6,%7}, {%8,%9}, {%0,%1,%2,%3};"
        : "+f"(d[0]), "+f"(d[1]), "+f"(d[2]), "+f"(d[3])
        : "r"(a0), "r"(a1), "r"(a2), "r"(a3), "r"(b0), "r"(b1));
}

// ---------------------------------------------------------------------------
// Elementwise tf32 rounding pass (rna -> zero-mean quantization error)
// ---------------------------------------------------------------------------
__global__ void round_tf32_kernel(const float* __restrict__ src,
                                  float* __restrict__ dst, int n4) {
    int i = blockIdx.x * blockDim.x + threadIdx.x;
    if (i < n4) {
        float4 v = ((const float4*)src)[i];
        float4 o;
        o.x = round_tf32(v.x); o.y = round_tf32(v.y);
        o.z = round_tf32(v.z); o.w = round_tf32(v.w);
        ((float4*)dst)[i] = o;
    }
}

// ---------------------------------------------------------------------------
// tf32 mma.sync GEMM: C[m][n] = sum_k A[m][k]*W[n][k]. M=4096,N=1024,K=1024.
// CTA: 256 thr (8 warps), tile 128x128, warp = 32m x 64n.
// K chunk = 32, 3-stage cp.async pipeline.
// Inputs must be tf32-pre-rounded. scatter=1 -> (B,H,S,dk) + tf32-round.
// ---------------------------------------------------------------------------
#define ASTRIDE 36                       // 32 + 4 pad (conflict-free frags)
#define CHUNKF  (128 * ASTRIDE)          // floats per tile-stage (A or B)
#define GSTAGES 3
#define GEMM_SMEM (GSTAGES * 2 * CHUNKF * (int)sizeof(float))   // 110592

__global__ __launch_bounds__(256) void gemm_tc_kernel(
    const float* __restrict__ A,
    const float* __restrict__ W0, const float* __restrict__ W1, const float* __restrict__ W2,
    float* __restrict__ C0, float* __restrict__ C1, float* __restrict__ C2,
    int scatter)
{
    const float* __restrict__ W = (blockIdx.z == 0) ? W0 : (blockIdx.z == 1) ? W1 : W2;
    float* __restrict__ C       = (blockIdx.z == 0) ? C0 : (blockIdx.z == 1) ? C1 : C2;

    extern __shared__ float sm[];

    const int tid  = threadIdx.x;
    const int wid  = tid >> 5;
    const int lane = tid & 31;
    const int g    = lane >> 2;          // 0..7 row group
    const int t    = lane & 3;           // 0..3 thread-in-group
    const int wm   = wid & 3;            // warp m index (32 rows each)
    const int wn   = wid >> 2;           // warp n index (64 cols each)
    const int nBase = blockIdx.x * 128;
    const int mBase = blockIdx.y * 128;

    // Global-load assignment: each thread: 4 float4 of A + 4 of B per chunk
    const int ldRow  = tid >> 1;         // 0..127
    const int ldHalf = tid & 1;          // 0/1 -> cols [0..15] or [16..31]
    const float* Ag = A + (size_t)(mBase + ldRow) * DMODEL + ldHalf * 16;
    const float* Wg = W + (size_t)(nBase + ldRow) * DMODEL + ldHalf * 16;

    float acc[2][8][4];
#pragma unroll
    for (int i = 0; i < 2; i++)
#pragma unroll
        for (int j = 0; j < 8; j++)
#pragma unroll
            for (int l = 0; l < 4; l++) acc[i][j][l] = 0.0f;

    const uint32_t smemA0 = smem_u32(sm);

    // issue loads for chunk c into stage s
    auto issue = [&](int c, int s) {
        uint32_t dA = smemA0 + (uint32_t)(s * 2 * CHUNKF + ldRow * ASTRIDE + ldHalf * 16) * 4u;
        uint32_t dB = dA + (uint32_t)CHUNKF * 4u;
        const float* aS = Ag + c * 32;
        const float* bS = Wg + c * 32;
#pragma unroll
        for (int i = 0; i < 4; i++) {
            cp_async16(dA + i * 16u, aS + i * 4);
            cp_async16(dB + i * 16u, bS + i * 4);
        }
    };

    issue(0, 0); CP_COMMIT();
    issue(1, 1); CP_COMMIT();

    const int NCHUNK = DMODEL / 32;   // 32
    for (int c = 0; c < NCHUNK; c++) {
        CP_WAIT(1);
        __syncthreads();
        if (c + 2 < NCHUNK) issue(c + 2, (c + 2) % GSTAGES);
        CP_COMMIT();

        const float* As = sm + (c % GSTAGES) * 2 * CHUNKF;
        const float* Bs = As + CHUNKF;
        const float* Aw = As + (wm * 32) * ASTRIDE;
        const float* Bw = Bs + (wn * 64) * ASTRIDE;

#pragma unroll
        for (int ks = 0; ks < 4; ks++) {
            const int kc = ks * 8;
            uint32_t a[2][4];
#pragma unroll
            for (int mt = 0; mt < 2; mt++) {
                const float* Ar = Aw + (mt * 16 + g) * ASTRIDE + kc;
                a[mt][0] = __float_as_uint(Ar[t]);
                a[mt][1] = __float_as_uint(Ar[8 * ASTRIDE + t]);
                a[mt][2] = __float_as_uint(Ar[t + 4]);
                a[mt][3] = __float_as_uint(Ar[8 * ASTRIDE + t + 4]);
            }
#pragma unroll
            for (int nt = 0; nt < 8; nt++) {
                const float* Br = Bw + (nt * 8 + g) * ASTRIDE + kc;
                uint32_t b0 = __float_as_uint(Br[t]);
                uint32_t b1 = __float_as_uint(Br[t + 4]);
                mma_tf32(acc[0][nt], a[0][0], a[0][1], a[0][2], a[0][3], b0, b1);
                mma_tf32(acc[1][nt], a[1][0], a[1][1], a[1][2], a[1][3], b0, b1);
            }
        }
    }

    // Epilogue: c0,c1 -> row r, cols 2t,2t+1 ; c2,c3 -> row r+8
#pragma unroll
    for (int mt = 0; mt < 2; mt++) {
#pragma unroll
        for (int half = 0; half < 2; half++) {
            const int m = mBase + wm * 32 + mt * 16 + g + half * 8;
#pragma unroll
            for (int nt = 0; nt < 8; nt++) {
                const int n = nBase + wn * 64 + nt * 8 + 2 * t;
                float2 v;
                v.x = acc[mt][nt][half * 2 + 0];
                v.y = acc[mt][nt][half * 2 + 1];
                if (scatter) {
                    v.x = round_tf32(v.x); v.y = round_tf32(v.y);
                    const int b = m >> 11, s = m & 2047;
                    const int head = n >> 6, d0 = n & 63;
                    *(float2*)&C[(((size_t)((b << 4) + head) * S_LEN + s) * DK + d0)] = v;
                } else {
                    *(float2*)&C[(size_t)m * DMODEL + n] = v;
                }
            }
        }
    }
}

// ---------------------------------------------------------------------------
// Flash attention with tf32 mma.sync.
// CTA: 256 thr (8 warps). Q block = 128 rows (16/warp). kv tile = 64.
// Q,K,V are tf32-pre-rounded by the projection GEMM epilogue.
// Output written tf32-rounded to g_att (B,S,D).
// ---------------------------------------------------------------------------
#define KSTR 68          // sK row stride (floats)
#define VSTR 72          // sV row stride
#define PSTR 68          // sP row stride (per-warp 16 x 68)
#define SK_F   (64 * KSTR)             // 4352
#define SV_F   (64 * VSTR)             // 4608
#define STAGE_F (SK_F + SV_F)          // 8960
#define SP_OFF (2 * STAGE_F)           // 17920
#define ATTN_F (SP_OFF + 8 * 16 * PSTR)
#define ATTN_SMEM (ATTN_F * (int)sizeof(float))   // 106496

__global__ __launch_bounds__(256) void attn_kernel(
    const float* __restrict__ Q, const float* __restrict__ K,
    const float* __restrict__ V, float* __restrict__ Oatt)
{
    extern __shared__ float sm[];

    const int tid  = threadIdx.x;
    const int wid  = tid >> 5;
    const int lane = tid & 31;
    const int g    = lane >> 2;
    const int t    = lane & 3;
    const int qb   = blockIdx.x;            // 0..15  (128 rows each)
    const int bh   = blockIdx.y;            // 0..31
    const int b    = bh >> 4;
    const int h    = bh & 15;

    float* sPw = sm + SP_OFF + wid * 16 * PSTR;

    // ---- Stage Q slice (16 rows) into own sP region, build persistent frags
    {
        const float* Qg = Q + ((size_t)bh * S_LEN + qb * 128 + wid * 16) * DK;
#pragma unroll
        for (int i = 0; i < 8; i++) {
            int q4 = lane + 32 * i;          // 0..255
            int r = q4 >> 4, qc = q4 & 15;
            *(float4*)&sPw[r * PSTR + qc * 4] = *(const float4*)&Qg[r * DK + qc * 4];
        }
        __syncwarp();
    }
    uint32_t qa[8][4];
#pragma unroll
    for (int ks = 0; ks < 8; ks++) {
        const float* Pr = sPw + g * PSTR + ks * 8;
        qa[ks][0] = __float_as_uint(Pr[t] * 0.125f);              // exact scale
        qa[ks][1] = __float_as_uint(Pr[8 * PSTR + t] * 0.125f);
        qa[ks][2] = __float_as_uint(Pr[t + 4] * 0.125f);
        qa[ks][3] = __float_as_uint(Pr[8 * PSTR + t + 4] * 0.125f);
    }
    __syncwarp();

    float o_[8][4];
#pragma unroll
    for (int nt = 0; nt < 8; nt++)
#pragma unroll
        for (int l = 0; l < 4; l++) o_[nt][l] = 0.0f;
    float m0 = -1e30f, m1 = -1e30f, l0 = 0.0f, l1 = 0.0f;

    const float* Kg = K + (size_t)bh * S_LEN * DK;
    const float* Vg = V + (size_t)bh * S_LEN * DK;
    const uint32_t smemB = smem_u32(sm);

    // K/V tile loader: 64 rows x 64 floats each
    auto issue = [&](int kv, int st) {
        uint32_t dK = smemB + (uint32_t)(st * STAGE_F) * 4u;
        uint32_t dV = dK + (uint32_t)SK_F * 4u;
        const float* kS = Kg + (size_t)kv * 64 * DK;
        const float* vS = Vg + (size_t)kv * 64 * DK;
#pragma unroll
        for (int i = 0; i < 4; i++) {
            int q4 = tid + 256 * i;          // 0..1023
            int r = q4 >> 4, qc = q4 & 15;
            cp_async16(dK + (uint32_t)(r * KSTR + qc * 4) * 4u, kS + r * DK + qc * 4);
            cp_async16(dV + (uint32_t)(r * VSTR + qc * 4) * 4u, vS + r * DK + qc * 4);
        }
    };

    issue(0, 0); CP_COMMIT();

    const int NKV = S_LEN / 64;   // 32
    for (int kv = 0; kv < NKV; kv++) {
        CP_WAIT(0);
        __syncthreads();
        if (kv + 1 < NKV) issue(kv + 1, (kv + 1) & 1);
        CP_COMMIT();

        const float* sK = sm + (kv & 1) * STAGE_F;
        const float* sV = sK + SK_F;

        // ---- scores S = (Q/8) K^T   (16 x 64 per warp)
        float s_[8][4];
#pragma unroll
        for (int nt = 0; nt < 8; nt++)
#pragma unroll
            for (int l = 0; l < 4; l++) s_[nt][l] = 0.0f;

#pragma unroll
        for (int ks = 0; ks < 8; ks++) {
#pragma unroll
            for (int nt = 0; nt < 8; nt++) {
                const float* Kr = sK + (nt * 8 + g) * KSTR + ks * 8;
                uint32_t b0 = __float_as_uint(Kr[t]);
                uint32_t b1 = __float_as_uint(Kr[t + 4]);
                mma_tf32(s_[nt], qa[ks][0], qa[ks][1], qa[ks][2], qa[ks][3], b0, b1);
            }
        }

        // ---- online softmax (rows g and g+8; lanes sharing g: xor 1,2)
        float mx0 = -1e30f, mx1 = -1e30f;
#pragma unroll
        for (int nt = 0; nt < 8; nt++) {
            mx0 = fmaxf(mx0, fmaxf(s_[nt][0], s_[nt][1]));
            mx1 = fmaxf(mx1, fmaxf(s_[nt][2], s_[nt][3]));
        }
        mx0 = fmaxf(mx0, __shfl_xor_sync(0xffffffffu, mx0, 1));
        mx0 = fmaxf(mx0, __shfl_xor_sync(0xffffffffu, mx0, 2));
        mx1 = fmaxf(mx1, __shfl_xor_sync(0xffffffffu, mx1, 1));
        mx1 = fmaxf(mx1, __shfl_xor_sync(0xffffffffu, mx1, 2));

        float mn0 = fmaxf(m0, mx0), mn1 = fmaxf(m1, mx1);
        float al0 = __expf(m0 - mn0), al1 = __expf(m1 - mn1);
        m0 = mn0; m1 = mn1;

        float s0 = 0.0f, s1 = 0.0f;
#pragma unroll
        for (int nt = 0; nt < 8; nt++) {
            s_[nt][0] = __expf(s_[nt][0] - mn0); s0 += s_[nt][0];
            s_[nt][1] = __expf(s_[nt][1] - mn0); s0 += s_[nt][1];
            s_[nt][2] = __expf(s_[nt][2] - mn1); s1 += s_[nt][2];
            s_[nt][3] = __expf(s_[nt][3] - mn1); s1 += s_[nt][3];
        }
        s0 += __shfl_xor_sync(0xffffffffu, s0, 1);
        s0 += __shfl_xor_sync(0xffffffffu, s0, 2);
        s1 += __shfl_xor_sync(0xffffffffu, s1, 1);
        s1 += __shfl_xor_sync(0xffffffffu, s1, 2);
        l0 = l0 * al0 + s0;
        l1 = l1 * al1 + s1;

#pragma unroll
        for (int nt = 0; nt < 8; nt++) {
            o_[nt][0] *= al0; o_[nt][1] *= al0;
            o_[nt][2] *= al1; o_[nt][3] *= al1;
        }

        // ---- stage P (tf32-rounded) into per-warp smem, D-layout -> A-layout
#pragma unroll
        for (int nt = 0; nt < 8; nt++) {
            float2 p01 = make_float2(round_tf32(s_[nt][0]), round_tf32(s_[nt][1]));
            float2 p23 = make_float2(round_tf32(s_[nt][2]), round_tf32(s_[nt][3]));
            *(float2*)&sPw[g * PSTR + nt * 8 + 2 * t]       = p01;
            *(float2*)&sPw[(g + 8) * PSTR + nt * 8 + 2 * t] = p23;
        }
        __syncwarp();

        // ---- O += P V   (16 x 64)
#pragma unroll
        for (int kt = 0; kt < 8; kt++) {
            const float* Pr = sPw + g * PSTR + kt * 8;
            uint32_t a0 = __float_as_uint(Pr[t]);
            uint32_t a1 = __float_as_uint(Pr[8 * PSTR + t]);
            uint32_t a2 = __float_as_uint(Pr[t + 4]);
            uint32_t a3 = __float_as_uint(Pr[8 * PSTR + t + 4]);
#pragma unroll
            for (int nt = 0; nt < 8; nt++) {
                const float* Vr = sV + (kt * 8 + t) * VSTR + nt * 8 + g;
                uint32_t b0 = __float_as_uint(Vr[0]);
                uint32_t b1 = __float_as_uint(Vr[4 * VSTR]);
                mma_tf32(o_[nt], a0, a1, a2, a3, b0, b1);
            }
        }
        __syncwarp();
    }

    // ---- epilogue: normalize, round to tf32, write (B,S,D)
    const float inv0 = 1.0f / l0, inv1 = 1.0f / l1;
    const int row0 = qb * 128 + wid * 16 + g;
#pragma unroll
    for (int nt = 0; nt < 8; nt++) {
        const int col = h * DK + nt * 8 + 2 * t;
        float2 v0, v1;
        v0.x = round_tf32(o_[nt][0] * inv0); v0.y = round_tf32(o_[nt][1] * inv0);
        v1.x = round_tf32(o_[nt][2] * inv1); v1.y = round_tf32(o_[nt][3] * inv1);
        *(float2*)&Oatt[((size_t)b * S_LEN + row0) * DMODEL + col]       = v0;
        *(float2*)&Oatt[((size_t)b * S_LEN + row0 + 8) * DMODEL + col]   = v1;
    }
}

// ---------------------------------------------------------------------------
extern "C" void kernel_launch(void* const* d_in, const int* in_sizes, int n_in,
                              void* d_out, int out_size)
{
    const float* x  = (const float*)d_in[0];
    const float* Wq = (const float*)d_in[1];
    const float* Wk = (const float*)d_in[2];
    const float* Wv = (const float*)d_in[3];
    const float* Wo = (const float*)d_in[4];
    float* out = (float*)d_out;

    float *qp, *kp, *vp, *attp, *rp;
    cudaGetSymbolAddress((void**)&qp,   g_q);
    cudaGetSymbolAddress((void**)&kp,   g_k);
    cudaGetSymbolAddress((void**)&vp,   g_v);
    cudaGetSymbolAddress((void**)&attp, g_att);
    cudaGetSymbolAddress((void**)&rp,   g_round);

    float* xr  = rp;                       // 4M floats
    float* wqr = rp + 4 * 1024 * 1024;
    float* wkr = rp + 5 * 1024 * 1024;
    float* wvr = rp + 6 * 1024 * 1024;
    float* wor = rp + 7 * 1024 * 1024;

    // 0) tf32 rna pre-rounding of GEMM inputs
    const int NX4 = (M_TOTAL * DMODEL) / 4;
    const int NW4 = (DMODEL * DMODEL) / 4;
    round_tf32_kernel<<<(NX4 + 255) / 256, 256>>>(x,  xr,  NX4);
    round_tf32_kernel<<<(NW4 + 255) / 256, 256>>>(Wq, wqr, NW4);
    round_tf32_kernel<<<(NW4 + 255) / 256, 256>>>(Wk, wkr, NW4);
    round_tf32_kernel<<<(NW4 + 255) / 256, 256>>>(Wv, wvr, NW4);
    round_tf32_kernel<<<(NW4 + 255) / 256, 256>>>(Wo, wor, NW4);

    cudaFuncSetAttribute(gemm_tc_kernel, cudaFuncAttributeMaxDynamicSharedMemorySize,
                         GEMM_SMEM);
    cudaFuncSetAttribute(attn_kernel, cudaFuncAttributeMaxDynamicSharedMemorySize,
                         ATTN_SMEM);

    // 1) Fused QKV projections (tf32 mma), scatter+round to (B,H,S,dk)
    dim3 gQKV(DMODEL / 128, M_TOTAL / 128, 3);
    gemm_tc_kernel<<<gQKV, 256, GEMM_SMEM>>>(xr, wqr, wkr, wvr, qp, kp, vp, 1);

    // 2) Flash attention (tf32 mma) -> (B,S,D), rounded
    dim3 gA(S_LEN / 128, BATCH * NHEADS);
    attn_kernel<<<gA, 256, ATTN_SMEM>>>(qp, kp, vp, attp);

    // 3) Output projection (tf32 mma) -> d_out
    dim3 gO(DMODEL / 128, M_TOTAL / 128, 1);
    gemm_tc_kernel<<<gO, 256, GEMM_SMEM>>>(attp, wor, wor, wor, out, out, out, 0);
}

// round 4
// speedup vs baseline: 4.4945x; 1.0671x over previous
#include <cuda_runtime.h>
#include <cstdint>

// Problem constants
#define S_LEN    2048
#define DMODEL   1024
#define NHEADS   16
#define DK       64
#define BATCH    2
#define M_TOTAL  (BATCH * S_LEN)   // 4096

// Scratch (allocation-free rule: __device__ globals)
__device__ float g_q[BATCH * NHEADS * S_LEN * DK];     // (B,H,S,dk) tf32-rounded
__device__ float g_k[BATCH * NHEADS * S_LEN * DK];
__device__ float g_v[BATCH * NHEADS * S_LEN * DK];
__device__ float g_att[BATCH * S_LEN * DMODEL];        // (B,S,D) tf32-rounded
__device__ float g_round[8 * 1024 * 1024];             // rounded x + 4 weights

// ---------------------------------------------------------------------------
// Helpers
// ---------------------------------------------------------------------------
__device__ __forceinline__ uint32_t smem_u32(const void* p) {
    uint32_t a;
    asm("{ .reg .u64 t; cvta.to.shared.u64 t, %1; cvt.u32.u64 %0, t; }"
        : "=r"(a) : "l"(p));
    return a;
}

__device__ __forceinline__ void cp_async16(uint32_t s, const void* g) {
    asm volatile("cp.async.cg.shared.global [%0], [%1], 16;" :: "r"(s), "l"(g));
}
#define CP_COMMIT() asm volatile("cp.async.commit_group;" ::: "memory")
#define CP_WAIT(n)  asm volatile("cp.async.wait_group %0;" :: "n"(n) : "memory")

__device__ __forceinline__ float round_tf32(float v) {
    uint32_t u;
    asm("cvt.rna.tf32.f32 %0, %1;" : "=r"(u) : "f"(v));
    return __uint_as_float(u);
}

// D(16x8) += A(16x8,row) * B(8x8,col)  -- tf32, fp32 accum
__device__ __forceinline__ void mma_tf32(float* d,
                                         uint32_t a0, uint32_t a1, uint32_t a2, uint32_t a3,
                                         uint32_t b0, uint32_t b1) {
    asm volatile(
        "mma.sync.aligned.m16n8k8.row.col.f32.tf32.tf32.f32 "
        "{%0,%1,%2,%3}, {%4,%5,%6,%7}, {%8,%9}, {%0,%1,%2,%3};"
        : "+f"(d[0]), "+f"(d[1]), "+f"(d[2]), "+f"(d[3])
        : "r"(a0), "r"(a1), "r"(a2), "r"(a3), "r"(b0), "r"(b1));
}

// ---------------------------------------------------------------------------
// Single fused tf32 rounding pass over x + 4 weights.
// Blocks [0,4096)  -> x (4096x1024 floats = 1M float4)
// Blocks [4096+1024*i, ...) -> weight i (1024x1024 = 256K float4)
// ---------------------------------------------------------------------------
__global__ __launch_bounds__(256) void round_all_kernel(
    const float* __restrict__ x,
    const float* __restrict__ wq, const float* __restrict__ wk,
    const float* __restrict__ wv, const float* __restrict__ wo,
    float* __restrict__ xr,
    float* __restrict__ wqr, float* __restrict__ wkr,
    float* __restrict__ wvr, float* __restrict__ wor)
{
    const int bidx = blockIdx.x;
    const float* src;
    float* dst;
    int off;
    if (bidx < 4096) { src = x; dst = xr; off = bidx; }
    else {
        const int i = (bidx - 4096) >> 10;
        off = (bidx - 4096) & 1023;
        src = (i == 0) ? wq : (i == 1) ? wk : (i == 2) ? wv : wo;
        dst = (i == 0) ? wqr : (i == 1) ? wkr : (i == 2) ? wvr : wor;
    }
    const int idx = off * 256 + threadIdx.x;
    float4 v = ((const float4*)src)[idx];
    float4 o;
    o.x = round_tf32(v.x); o.y = round_tf32(v.y);
    o.z = round_tf32(v.z); o.w = round_tf32(v.w);
    ((float4*)dst)[idx] = o;
}

// ---------------------------------------------------------------------------
// tf32 mma.sync GEMM: C[m][n] = sum_k A[m][k]*W[n][k]. M=4096,N=1024,K=1024.
// CTA: 256 thr (8 warps), tile 128x128, warp = 32m x 64n.
// K chunk = 32, 3-stage cp.async pipeline.
// Inputs must be tf32-pre-rounded. scatter=1 -> (B,H,S,dk) + tf32-round.
// ---------------------------------------------------------------------------
#define ASTRIDE 36                       // 32 + 4 pad (conflict-free frags)
#define CHUNKF  (128 * ASTRIDE)          // floats per tile-stage (A or B)
#define GSTAGES 3
#define GEMM_SMEM (GSTAGES * 2 * CHUNKF * (int)sizeof(float))   // 110592

__global__ __launch_bounds__(256) void gemm_tc_kernel(
    const float* __restrict__ A,
    const float* __restrict__ W0, const float* __restrict__ W1, const float* __restrict__ W2,
    float* __restrict__ C0, float* __restrict__ C1, float* __restrict__ C2,
    int scatter)
{
    const float* __restrict__ W = (blockIdx.z == 0) ? W0 : (blockIdx.z == 1) ? W1 : W2;
    float* __restrict__ C       = (blockIdx.z == 0) ? C0 : (blockIdx.z == 1) ? C1 : C2;

    extern __shared__ float sm[];

    const int tid  = threadIdx.x;
    const int wid  = tid >> 5;
    const int lane = tid & 31;
    const int g    = lane >> 2;          // 0..7 row group
    const int t    = lane & 3;           // 0..3 thread-in-group
    const int wm   = wid & 3;            // warp m index (32 rows each)
    const int wn   = wid >> 2;           // warp n index (64 cols each)
    const int nBase = blockIdx.x * 128;
    const int mBase = blockIdx.y * 128;

    const int ldRow  = tid >> 1;         // 0..127
    const int ldHalf = tid & 1;          // 0/1 -> cols [0..15] or [16..31]
    const float* Ag = A + (size_t)(mBase + ldRow) * DMODEL + ldHalf * 16;
    const float* Wg = W + (size_t)(nBase + ldRow) * DMODEL + ldHalf * 16;

    float acc[2][8][4];
#pragma unroll
    for (int i = 0; i < 2; i++)
#pragma unroll
        for (int j = 0; j < 8; j++)
#pragma unroll
            for (int l = 0; l < 4; l++) acc[i][j][l] = 0.0f;

    const uint32_t smemA0 = smem_u32(sm);

    auto issue = [&](int c, int s) {
        uint32_t dA = smemA0 + (uint32_t)(s * 2 * CHUNKF + ldRow * ASTRIDE + ldHalf * 16) * 4u;
        uint32_t dB = dA + (uint32_t)CHUNKF * 4u;
        const float* aS = Ag + c * 32;
        const float* bS = Wg + c * 32;
#pragma unroll
        for (int i = 0; i < 4; i++) {
            cp_async16(dA + i * 16u, aS + i * 4);
            cp_async16(dB + i * 16u, bS + i * 4);
        }
    };

    issue(0, 0); CP_COMMIT();
    issue(1, 1); CP_COMMIT();

    const int NCHUNK = DMODEL / 32;   // 32
    for (int c = 0; c < NCHUNK; c++) {
        CP_WAIT(1);
        __syncthreads();
        if (c + 2 < NCHUNK) issue(c + 2, (c + 2) % GSTAGES);
        CP_COMMIT();

        const float* As = sm + (c % GSTAGES) * 2 * CHUNKF;
        const float* Bs = As + CHUNKF;
        const float* Aw = As + (wm * 32) * ASTRIDE;
        const float* Bw = Bs + (wn * 64) * ASTRIDE;

#pragma unroll
        for (int ks = 0; ks < 4; ks++) {
            const int kc = ks * 8;
            uint32_t a[2][4];
#pragma unroll
            for (int mt = 0; mt < 2; mt++) {
                const float* Ar = Aw + (mt * 16 + g) * ASTRIDE + kc;
                a[mt][0] = __float_as_uint(Ar[t]);
                a[mt][1] = __float_as_uint(Ar[8 * ASTRIDE + t]);
                a[mt][2] = __float_as_uint(Ar[t + 4]);
                a[mt][3] = __float_as_uint(Ar[8 * ASTRIDE + t + 4]);
            }
#pragma unroll
            for (int nt = 0; nt < 8; nt++) {
                const float* Br = Bw + (nt * 8 + g) * ASTRIDE + kc;
                uint32_t b0 = __float_as_uint(Br[t]);
                uint32_t b1 = __float_as_uint(Br[t + 4]);
                mma_tf32(acc[0][nt], a[0][0], a[0][1], a[0][2], a[0][3], b0, b1);
                mma_tf32(acc[1][nt], a[1][0], a[1][1], a[1][2], a[1][3], b0, b1);
            }
        }
    }

    // Epilogue: c0,c1 -> row r, cols 2t,2t+1 ; c2,c3 -> row r+8
#pragma unroll
    for (int mt = 0; mt < 2; mt++) {
#pragma unroll
        for (int half = 0; half < 2; half++) {
            const int m = mBase + wm * 32 + mt * 16 + g + half * 8;
#pragma unroll
            for (int nt = 0; nt < 8; nt++) {
                const int n = nBase + wn * 64 + nt * 8 + 2 * t;
                float2 v;
                v.x = acc[mt][nt][half * 2 + 0];
                v.y = acc[mt][nt][half * 2 + 1];
                if (scatter) {
                    v.x = round_tf32(v.x); v.y = round_tf32(v.y);
                    const int b = m >> 11, s = m & 2047;
                    const int head = n >> 6, d0 = n & 63;
                    *(float2*)&C[(((size_t)((b << 4) + head) * S_LEN + s) * DK + d0)] = v;
                } else {
                    *(float2*)&C[(size_t)m * DMODEL + n] = v;
                }
            }
        }
    }
}

// ---------------------------------------------------------------------------
// Flash attention with tf32 mma.sync.
// CTA: 256 thr (8 warps). Q block = 256 rows (32 rows = 2 m-tiles per warp).
// Each K/V fragment is reused across both m-tiles (halved B-operand LDS).
// kv tile = 64, 2-stage cp.async. Q staged once (pre-scaled by 1/8) into a
// dedicated smem region; P staged per-warp into its own region.
// ---------------------------------------------------------------------------
#define KSTR 68          // sK row stride (floats)
#define VSTR 72          // sV row stride
#define PSTR 68          // sP/sQ row stride
#define SK_F   (64 * KSTR)             // 4352
#define SV_F   (64 * VSTR)             // 4608
#define STAGE_F (SK_F + SV_F)          // 8960
#define SP_OFF (2 * STAGE_F)           // 17920
#define SQ_OFF (SP_OFF + 8 * 32 * PSTR)        // 17920 + 17408
#define ATTN_F (SQ_OFF + 8 * 32 * PSTR)        // 52736 floats
#define ATTN_SMEM (ATTN_F * (int)sizeof(float))   // 210944 bytes

__global__ __launch_bounds__(256) void attn_kernel(
    const float* __restrict__ Q, const float* __restrict__ K,
    const float* __restrict__ V, float* __restrict__ Oatt)
{
    extern __shared__ float sm[];

    const int tid  = threadIdx.x;
    const int wid  = tid >> 5;
    const int lane = tid & 31;
    const int g    = lane >> 2;
    const int t    = lane & 3;
    const int qb   = blockIdx.x;            // 0..7  (256 rows each)
    const int bh   = blockIdx.y;            // 0..31
    const int b    = bh >> 4;
    const int h    = bh & 15;

    float* sPw = sm + SP_OFF + wid * 32 * PSTR;
    float* sQw = sm + SQ_OFF + wid * 32 * PSTR;

    // ---- Stage Q slice (32 rows per warp), pre-scaled by 1/sqrt(dk)=0.125
    {
        const float* Qg = Q + ((size_t)bh * S_LEN + qb * 256 + wid * 32) * DK;
#pragma unroll
        for (int i = 0; i < 16; i++) {
            int idx = lane + 32 * i;         // 0..511
            int r = idx >> 4, c = idx & 15;
            float4 v = *(const float4*)&Qg[r * DK + c * 4];
            v.x *= 0.125f; v.y *= 0.125f; v.z *= 0.125f; v.w *= 0.125f;
            *(float4*)&sQw[r * PSTR + c * 4] = v;
        }
        __syncwarp();
    }

    float o_[2][8][4];
#pragma unroll
    for (int mt = 0; mt < 2; mt++)
#pragma unroll
        for (int nt = 0; nt < 8; nt++)
#pragma unroll
            for (int l = 0; l < 4; l++) o_[mt][nt][l] = 0.0f;
    float mrow[2][2] = {{-1e30f, -1e30f}, {-1e30f, -1e30f}};
    float lrow[2][2] = {{0.0f, 0.0f}, {0.0f, 0.0f}};

    const float* Kg = K + (size_t)bh * S_LEN * DK;
    const float* Vg = V + (size_t)bh * S_LEN * DK;
    const uint32_t smemB = smem_u32(sm);

    auto issue = [&](int kv, int st) {
        uint32_t dK = smemB + (uint32_t)(st * STAGE_F) * 4u;
        uint32_t dV = dK + (uint32_t)SK_F * 4u;
        const float* kS = Kg + (size_t)kv * 64 * DK;
        const float* vS = Vg + (size_t)kv * 64 * DK;
#pragma unroll
        for (int i = 0; i < 4; i++) {
            int q4 = tid + 256 * i;          // 0..1023
            int r = q4 >> 4, qc = q4 & 15;
            cp_async16(dK + (uint32_t)(r * KSTR + qc * 4) * 4u, kS + r * DK + qc * 4);
            cp_async16(dV + (uint32_t)(r * VSTR + qc * 4) * 4u, vS + r * DK + qc * 4);
        }
    };

    issue(0, 0); CP_COMMIT();

    const int NKV = S_LEN / 64;   // 32
    for (int kv = 0; kv < NKV; kv++) {
        CP_WAIT(0);
        __syncthreads();
        if (kv + 1 < NKV) issue(kv + 1, (kv + 1) & 1);
        CP_COMMIT();

        const float* sK = sm + (kv & 1) * STAGE_F;
        const float* sV = sK + SK_F;

        // ---- scores S = (Q/8) K^T   (32 x 64 per warp; K frags reused x2)
        float s_[2][8][4];
#pragma unroll
        for (int mt = 0; mt < 2; mt++)
#pragma unroll
            for (int nt = 0; nt < 8; nt++)
#pragma unroll
                for (int l = 0; l < 4; l++) s_[mt][nt][l] = 0.0f;

#pragma unroll
        for (int ks = 0; ks < 8; ks++) {
            uint32_t a[2][4];
#pragma unroll
            for (int mt = 0; mt < 2; mt++) {
                const float* Ar = sQw + (mt * 16 + g) * PSTR + ks * 8;
                a[mt][0] = __float_as_uint(Ar[t]);
                a[mt][1] = __float_as_uint(Ar[8 * PSTR + t]);
                a[mt][2] = __float_as_uint(Ar[t + 4]);
                a[mt][3] = __float_as_uint(Ar[8 * PSTR + t + 4]);
            }
#pragma unroll
            for (int nt = 0; nt < 8; nt++) {
                const float* Kr = sK + (nt * 8 + g) * KSTR + ks * 8;
                uint32_t b0 = __float_as_uint(Kr[t]);
                uint32_t b1 = __float_as_uint(Kr[t + 4]);
                mma_tf32(s_[0][nt], a[0][0], a[0][1], a[0][2], a[0][3], b0, b1);
                mma_tf32(s_[1][nt], a[1][0], a[1][1], a[1][2], a[1][3], b0, b1);
            }
        }

        // ---- online softmax per m-tile (rows g, g+8; lanes sharing g: xor 1,2)
#pragma unroll
        for (int mt = 0; mt < 2; mt++) {
            float mx0 = -1e30f, mx1 = -1e30f;
#pragma unroll
            for (int nt = 0; nt < 8; nt++) {
                mx0 = fmaxf(mx0, fmaxf(s_[mt][nt][0], s_[mt][nt][1]));
                mx1 = fmaxf(mx1, fmaxf(s_[mt][nt][2], s_[mt][nt][3]));
            }
            mx0 = fmaxf(mx0, __shfl_xor_sync(0xffffffffu, mx0, 1));
            mx0 = fmaxf(mx0, __shfl_xor_sync(0xffffffffu, mx0, 2));
            mx1 = fmaxf(mx1, __shfl_xor_sync(0xffffffffu, mx1, 1));
            mx1 = fmaxf(mx1, __shfl_xor_sync(0xffffffffu, mx1, 2));

            float mn0 = fmaxf(mrow[mt][0], mx0), mn1 = fmaxf(mrow[mt][1], mx1);
            float al0 = __expf(mrow[mt][0] - mn0), al1 = __expf(mrow[mt][1] - mn1);
            mrow[mt][0] = mn0; mrow[mt][1] = mn1;

            float s0 = 0.0f, s1 = 0.0f;
#pragma unroll
            for (int nt = 0; nt < 8; nt++) {
                s_[mt][nt][0] = __expf(s_[mt][nt][0] - mn0); s0 += s_[mt][nt][0];
                s_[mt][nt][1] = __expf(s_[mt][nt][1] - mn0); s0 += s_[mt][nt][1];
                s_[mt][nt][2] = __expf(s_[mt][nt][2] - mn1); s1 += s_[mt][nt][2];
                s_[mt][nt][3] = __expf(s_[mt][nt][3] - mn1); s1 += s_[mt][nt][3];
            }
            s0 += __shfl_xor_sync(0xffffffffu, s0, 1);
            s0 += __shfl_xor_sync(0xffffffffu, s0, 2);
            s1 += __shfl_xor_sync(0xffffffffu, s1, 1);
            s1 += __shfl_xor_sync(0xffffffffu, s1, 2);
            lrow[mt][0] = lrow[mt][0] * al0 + s0;
            lrow[mt][1] = lrow[mt][1] * al1 + s1;

#pragma unroll
            for (int nt = 0; nt < 8; nt++) {
                o_[mt][nt][0] *= al0; o_[mt][nt][1] *= al0;
                o_[mt][nt][2] *= al1; o_[mt][nt][3] *= al1;
            }

            // stage P (tf32-rounded) D-layout -> A-layout
#pragma unroll
            for (int nt = 0; nt < 8; nt++) {
                float2 p01 = make_float2(round_tf32(s_[mt][nt][0]), round_tf32(s_[mt][nt][1]));
                float2 p23 = make_float2(round_tf32(s_[mt][nt][2]), round_tf32(s_[mt][nt][3]));
                *(float2*)&sPw[(mt * 16 + g) * PSTR + nt * 8 + 2 * t]     = p01;
                *(float2*)&sPw[(mt * 16 + g + 8) * PSTR + nt * 8 + 2 * t] = p23;
            }
        }
        __syncwarp();

        // ---- O += P V   (32 x 64 per warp; V frags reused x2)
#pragma unroll
        for (int kt = 0; kt < 8; kt++) {
            uint32_t a[2][4];
#pragma unroll
            for (int mt = 0; mt < 2; mt++) {
                const float* Pr = sPw + (mt * 16 + g) * PSTR + kt * 8;
                a[mt][0] = __float_as_uint(Pr[t]);
                a[mt][1] = __float_as_uint(Pr[8 * PSTR + t]);
                a[mt][2] = __float_as_uint(Pr[t + 4]);
                a[mt][3] = __float_as_uint(Pr[8 * PSTR + t + 4]);
            }
#pragma unroll
            for (int nt = 0; nt < 8; nt++) {
                const float* Vr = sV + (kt * 8 + t) * VSTR + nt * 8 + g;
                uint32_t b0 = __float_as_uint(Vr[0]);
                uint32_t b1 = __float_as_uint(Vr[4 * VSTR]);
                mma_tf32(o_[0][nt], a[0][0], a[0][1], a[0][2], a[0][3], b0, b1);
                mma_tf32(o_[1][nt], a[1][0], a[1][1], a[1][2], a[1][3], b0, b1);
            }
        }
        __syncwarp();
    }

    // ---- epilogue: normalize, round to tf32, write (B,S,D)
#pragma unroll
    for (int mt = 0; mt < 2; mt++) {
        const float inv0 = 1.0f / lrow[mt][0], inv1 = 1.0f / lrow[mt][1];
        const int row0 = qb * 256 + wid * 32 + mt * 16 + g;
#pragma unroll
        for (int nt = 0; nt < 8; nt++) {
            const int col = h * DK + nt * 8 + 2 * t;
            float2 v0, v1;
            v0.x = round_tf32(o_[mt][nt][0] * inv0); v0.y = round_tf32(o_[mt][nt][1] * inv0);
            v1.x = round_tf32(o_[mt][nt][2] * inv1); v1.y = round_tf32(o_[mt][nt][3] * inv1);
            *(float2*)&Oatt[((size_t)b * S_LEN + row0) * DMODEL + col]     = v0;
            *(float2*)&Oatt[((size_t)b * S_LEN + row0 + 8) * DMODEL + col] = v1;
        }
    }
}

// ---------------------------------------------------------------------------
extern "C" void kernel_launch(void* const* d_in, const int* in_sizes, int n_in,
                              void* d_out, int out_size)
{
    const float* x  = (const float*)d_in[0];
    const float* Wq = (const float*)d_in[1];
    const float* Wk = (const float*)d_in[2];
    const float* Wv = (const float*)d_in[3];
    const float* Wo = (const float*)d_in[4];
    float* out = (float*)d_out;

    float *qp, *kp, *vp, *attp, *rp;
    cudaGetSymbolAddress((void**)&qp,   g_q);
    cudaGetSymbolAddress((void**)&kp,   g_k);
    cudaGetSymbolAddress((void**)&vp,   g_v);
    cudaGetSymbolAddress((void**)&attp, g_att);
    cudaGetSymbolAddress((void**)&rp,   g_round);

    float* xr  = rp;                       // 4M floats
    float* wqr = rp + 4 * 1024 * 1024;
    float* wkr = rp + 5 * 1024 * 1024;
    float* wvr = rp + 6 * 1024 * 1024;
    float* wor = rp + 7 * 1024 * 1024;

    // 0) single fused tf32 rna pre-rounding of all GEMM inputs
    round_all_kernel<<<8192, 256>>>(x, Wq, Wk, Wv, Wo, xr, wqr, wkr, wvr, wor);

    cudaFuncSetAttribute(gemm_tc_kernel, cudaFuncAttributeMaxDynamicSharedMemorySize,
                         GEMM_SMEM);
    cudaFuncSetAttribute(attn_kernel, cudaFuncAttributeMaxDynamicSharedMemorySize,
                         ATTN_SMEM);

    // 1) Fused QKV projections (tf32 mma), scatter+round to (B,H,S,dk)
    dim3 gQKV(DMODEL / 128, M_TOTAL / 128, 3);
    gemm_tc_kernel<<<gQKV, 256, GEMM_SMEM>>>(xr, wqr, wkr, wvr, qp, kp, vp, 1);

    // 2) Flash attention (tf32 mma) -> (B,S,D), rounded
    dim3 gA(S_LEN / 256, BATCH * NHEADS);
    attn_kernel<<<gA, 256, ATTN_SMEM>>>(qp, kp, vp, attp);

    // 3) Output projection (tf32 mma) -> d_out
    dim3 gO(DMODEL / 128, M_TOTAL / 128, 1);
    gemm_tc_kernel<<<gO, 256, GEMM_SMEM>>>(attp, wor, wor, wor, out, out, out, 0);
}

// round 5
// speedup vs baseline: 4.6053x; 1.0247x over previous
#include <cuda_runtime.h>
#include <cstdint>

// Problem constants
#define S_LEN    2048
#define DMODEL   1024
#define NHEADS   16
#define DK       64
#define BATCH    2
#define M_TOTAL  (BATCH * S_LEN)   // 4096

// Scratch (allocation-free rule: __device__ globals)
__device__ float g_q[BATCH * NHEADS * S_LEN * DK];     // (B,H,S,dk) tf32-rounded
__device__ float g_k[BATCH * NHEADS * S_LEN * DK];
__device__ float g_v[BATCH * NHEADS * S_LEN * DK];
__device__ float g_att[BATCH * S_LEN * DMODEL];        // (B,S,D) tf32-rounded
__device__ float g_round[8 * 1024 * 1024];             // rounded x + 4 weights

// ---------------------------------------------------------------------------
// Helpers
// ---------------------------------------------------------------------------
__device__ __forceinline__ uint32_t smem_u32(const void* p) {
    uint32_t a;
    asm("{ .reg .u64 t; cvta.to.shared.u64 t, %1; cvt.u32.u64 %0, t; }"
        : "=r"(a) : "l"(p));
    return a;
}

__device__ __forceinline__ void cp_async16(uint32_t s, const void* g) {
    asm volatile("cp.async.cg.shared.global [%0], [%1], 16;" :: "r"(s), "l"(g));
}
#define CP_COMMIT() asm volatile("cp.async.commit_group;" ::: "memory")
#define CP_WAIT(n)  asm volatile("cp.async.wait_group %0;" :: "n"(n) : "memory")

__device__ __forceinline__ float round_tf32(float v) {
    uint32_t u;
    asm("cvt.rna.tf32.f32 %0, %1;" : "=r"(u) : "f"(v));
    return __uint_as_float(u);
}

// D(16x8) += A(16x8,row) * B(8x8,col)  -- tf32, fp32 accum
__device__ __forceinline__ void mma_tf32(float* d,
                                         uint32_t a0, uint32_t a1, uint32_t a2, uint32_t a3,
                                         uint32_t b0, uint32_t b1) {
    asm volatile(
        "mma.sync.aligned.m16n8k8.row.col.f32.tf32.tf32.f32 "
        "{%0,%1,%2,%3}, {%4,%5,%6,%7}, {%8,%9}, {%0,%1,%2,%3};"
        : "+f"(d[0]), "+f"(d[1]), "+f"(d[2]), "+f"(d[3])
        : "r"(a0), "r"(a1), "r"(a2), "r"(a3), "r"(b0), "r"(b1));
}

// ---------------------------------------------------------------------------
// Single fused tf32 rounding pass over x + 4 weights.
// ---------------------------------------------------------------------------
__global__ __launch_bounds__(256) void round_all_kernel(
    const float* __restrict__ x,
    const float* __restrict__ wq, const float* __restrict__ wk,
    const float* __restrict__ wv, const float* __restrict__ wo,
    float* __restrict__ xr,
    float* __restrict__ wqr, float* __restrict__ wkr,
    float* __restrict__ wvr, float* __restrict__ wor)
{
    const int bidx = blockIdx.x;
    const float* src;
    float* dst;
    int off;
    if (bidx < 4096) { src = x; dst = xr; off = bidx; }
    else {
        const int i = (bidx - 4096) >> 10;
        off = (bidx - 4096) & 1023;
        src = (i == 0) ? wq : (i == 1) ? wk : (i == 2) ? wv : wo;
        dst = (i == 0) ? wqr : (i == 1) ? wkr : (i == 2) ? wvr : wor;
    }
    const int idx = off * 256 + threadIdx.x;
    float4 v = ((const float4*)src)[idx];
    float4 o;
    o.x = round_tf32(v.x); o.y = round_tf32(v.y);
    o.z = round_tf32(v.z); o.w = round_tf32(v.w);
    ((float4*)dst)[idx] = o;
}

// ---------------------------------------------------------------------------
// tf32 mma.sync GEMM: C[m][n] = sum_k A[m][k]*W[n][k]. M=4096,N=1024,K=1024.
// CTA: 256 thr (8 warps), tile 128x128, warp = 32m x 64n.
// K chunk = 32, 2-stage cp.async double-buffer -> 73.7KB smem -> 2 CTAs/SM.
// Inputs must be tf32-pre-rounded. scatter=1 -> (B,H,S,dk) + tf32-round.
// ---------------------------------------------------------------------------
#define ASTRIDE 36                       // 32 + 4 pad (conflict-free frags)
#define CHUNKF  (128 * ASTRIDE)          // floats per tile-stage (A or B)
#define GSTAGES 2
#define GEMM_SMEM (GSTAGES * 2 * CHUNKF * (int)sizeof(float))   // 73728

__global__ __launch_bounds__(256, 2) void gemm_tc_kernel(
    const float* __restrict__ A,
    const float* __restrict__ W0, const float* __restrict__ W1, const float* __restrict__ W2,
    float* __restrict__ C0, float* __restrict__ C1, float* __restrict__ C2,
    int scatter)
{
    const float* __restrict__ W = (blockIdx.z == 0) ? W0 : (blockIdx.z == 1) ? W1 : W2;
    float* __restrict__ C       = (blockIdx.z == 0) ? C0 : (blockIdx.z == 1) ? C1 : C2;

    extern __shared__ float sm[];

    const int tid  = threadIdx.x;
    const int wid  = tid >> 5;
    const int lane = tid & 31;
    const int g    = lane >> 2;          // 0..7 row group
    const int t    = lane & 3;           // 0..3 thread-in-group
    const int wm   = wid & 3;            // warp m index (32 rows each)
    const int wn   = wid >> 2;           // warp n index (64 cols each)
    const int nBase = blockIdx.x * 128;
    const int mBase = blockIdx.y * 128;

    const int ldRow  = tid >> 1;         // 0..127
    const int ldHalf = tid & 1;          // 0/1 -> cols [0..15] or [16..31]
    const float* Ag = A + (size_t)(mBase + ldRow) * DMODEL + ldHalf * 16;
    const float* Wg = W + (size_t)(nBase + ldRow) * DMODEL + ldHalf * 16;

    float acc[2][8][4];
#pragma unroll
    for (int i = 0; i < 2; i++)
#pragma unroll
        for (int j = 0; j < 8; j++)
#pragma unroll
            for (int l = 0; l < 4; l++) acc[i][j][l] = 0.0f;

    const uint32_t smemA0 = smem_u32(sm);

    auto issue = [&](int c, int s) {
        uint32_t dA = smemA0 + (uint32_t)(s * 2 * CHUNKF + ldRow * ASTRIDE + ldHalf * 16) * 4u;
        uint32_t dB = dA + (uint32_t)CHUNKF * 4u;
        const float* aS = Ag + c * 32;
        const float* bS = Wg + c * 32;
#pragma unroll
        for (int i = 0; i < 4; i++) {
            cp_async16(dA + i * 16u, aS + i * 4);
            cp_async16(dB + i * 16u, bS + i * 4);
        }
    };

    issue(0, 0); CP_COMMIT();

    const int NCHUNK = DMODEL / 32;   // 32
    for (int c = 0; c < NCHUNK; c++) {
        CP_WAIT(0);           // chunk c resident
        __syncthreads();      // visible to all warps; stage (c+1)&1 free to refill
        if (c + 1 < NCHUNK) issue(c + 1, (c + 1) & 1);
        CP_COMMIT();          // (empty group in last iter keeps accounting simple)

        const float* As = sm + (c & 1) * 2 * CHUNKF;
        const float* Bs = As + CHUNKF;
        const float* Aw = As + (wm * 32) * ASTRIDE;
        const float* Bw = Bs + (wn * 64) * ASTRIDE;

#pragma unroll
        for (int ks = 0; ks < 4; ks++) {
            const int kc = ks * 8;
            uint32_t a[2][4];
#pragma unroll
            for (int mt = 0; mt < 2; mt++) {
                const float* Ar = Aw + (mt * 16 + g) * ASTRIDE + kc;
                a[mt][0] = __float_as_uint(Ar[t]);
                a[mt][1] = __float_as_uint(Ar[8 * ASTRIDE + t]);
                a[mt][2] = __float_as_uint(Ar[t + 4]);
                a[mt][3] = __float_as_uint(Ar[8 * ASTRIDE + t + 4]);
            }
#pragma unroll
            for (int nt = 0; nt < 8; nt++) {
                const float* Br = Bw + (nt * 8 + g) * ASTRIDE + kc;
                uint32_t b0 = __float_as_uint(Br[t]);
                uint32_t b1 = __float_as_uint(Br[t + 4]);
                mma_tf32(acc[0][nt], a[0][0], a[0][1], a[0][2], a[0][3], b0, b1);
                mma_tf32(acc[1][nt], a[1][0], a[1][1], a[1][2], a[1][3], b0, b1);
            }
        }
    }

    // Epilogue: c0,c1 -> row r, cols 2t,2t+1 ; c2,c3 -> row r+8
#pragma unroll
    for (int mt = 0; mt < 2; mt++) {
#pragma unroll
        for (int half = 0; half < 2; half++) {
            const int m = mBase + wm * 32 + mt * 16 + g + half * 8;
#pragma unroll
            for (int nt = 0; nt < 8; nt++) {
                const int n = nBase + wn * 64 + nt * 8 + 2 * t;
                float2 v;
                v.x = acc[mt][nt][half * 2 + 0];
                v.y = acc[mt][nt][half * 2 + 1];
                if (scatter) {
                    v.x = round_tf32(v.x); v.y = round_tf32(v.y);
                    const int b = m >> 11, s = m & 2047;
                    const int head = n >> 6, d0 = n & 63;
                    *(float2*)&C[(((size_t)((b << 4) + head) * S_LEN + s) * DK + d0)] = v;
                } else {
                    *(float2*)&C[(size_t)m * DMODEL + n] = v;
                }
            }
        }
    }
}

// ---------------------------------------------------------------------------
// Flash attention with tf32 mma.sync (unchanged from round 4).
// CTA: 256 thr (8 warps). Q block = 256 rows (32 rows = 2 m-tiles per warp).
// ---------------------------------------------------------------------------
#define KSTR 68          // sK row stride (floats)
#define VSTR 72          // sV row stride
#define PSTR 68          // sP/sQ row stride
#define SK_F   (64 * KSTR)             // 4352
#define SV_F   (64 * VSTR)             // 4608
#define STAGE_F (SK_F + SV_F)          // 8960
#define SP_OFF (2 * STAGE_F)           // 17920
#define SQ_OFF (SP_OFF + 8 * 32 * PSTR)
#define ATTN_F (SQ_OFF + 8 * 32 * PSTR)
#define ATTN_SMEM (ATTN_F * (int)sizeof(float))   // 210944 bytes

__global__ __launch_bounds__(256) void attn_kernel(
    const float* __restrict__ Q, const float* __restrict__ K,
    const float* __restrict__ V, float* __restrict__ Oatt)
{
    extern __shared__ float sm[];

    const int tid  = threadIdx.x;
    const int wid  = tid >> 5;
    const int lane = tid & 31;
    const int g    = lane >> 2;
    const int t    = lane & 3;
    const int qb   = blockIdx.x;            // 0..7  (256 rows each)
    const int bh   = blockIdx.y;            // 0..31
    const int b    = bh >> 4;
    const int h    = bh & 15;

    float* sPw = sm + SP_OFF + wid * 32 * PSTR;
    float* sQw = sm + SQ_OFF + wid * 32 * PSTR;

    // ---- Stage Q slice (32 rows per warp), pre-scaled by 1/sqrt(dk)=0.125
    {
        const float* Qg = Q + ((size_t)bh * S_LEN + qb * 256 + wid * 32) * DK;
#pragma unroll
        for (int i = 0; i < 16; i++) {
            int idx = lane + 32 * i;
            int r = idx >> 4, c = idx & 15;
            float4 v = *(const float4*)&Qg[r * DK + c * 4];
            v.x *= 0.125f; v.y *= 0.125f; v.z *= 0.125f; v.w *= 0.125f;
            *(float4*)&sQw[r * PSTR + c * 4] = v;
        }
        __syncwarp();
    }

    float o_[2][8][4];
#pragma unroll
    for (int mt = 0; mt < 2; mt++)
#pragma unroll
        for (int nt = 0; nt < 8; nt++)
#pragma unroll
            for (int l = 0; l < 4; l++) o_[mt][nt][l] = 0.0f;
    float mrow[2][2] = {{-1e30f, -1e30f}, {-1e30f, -1e30f}};
    float lrow[2][2] = {{0.0f, 0.0f}, {0.0f, 0.0f}};

    const float* Kg = K + (size_t)bh * S_LEN * DK;
    const float* Vg = V + (size_t)bh * S_LEN * DK;
    const uint32_t smemB = smem_u32(sm);

    auto issue = [&](int kv, int st) {
        uint32_t dK = smemB + (uint32_t)(st * STAGE_F) * 4u;
        uint32_t dV = dK + (uint32_t)SK_F * 4u;
        const float* kS = Kg + (size_t)kv * 64 * DK;
        const float* vS = Vg + (size_t)kv * 64 * DK;
#pragma unroll
        for (int i = 0; i < 4; i++) {
            int q4 = tid + 256 * i;
            int r = q4 >> 4, qc = q4 & 15;
            cp_async16(dK + (uint32_t)(r * KSTR + qc * 4) * 4u, kS + r * DK + qc * 4);
            cp_async16(dV + (uint32_t)(r * VSTR + qc * 4) * 4u, vS + r * DK + qc * 4);
        }
    };

    issue(0, 0); CP_COMMIT();

    const int NKV = S_LEN / 64;   // 32
    for (int kv = 0; kv < NKV; kv++) {
        CP_WAIT(0);
        __syncthreads();
        if (kv + 1 < NKV) issue(kv + 1, (kv + 1) & 1);
        CP_COMMIT();

        const float* sK = sm + (kv & 1) * STAGE_F;
        const float* sV = sK + SK_F;

        // ---- scores S = (Q/8) K^T   (32 x 64 per warp; K frags reused x2)
        float s_[2][8][4];
#pragma unroll
        for (int mt = 0; mt < 2; mt++)
#pragma unroll
            for (int nt = 0; nt < 8; nt++)
#pragma unroll
                for (int l = 0; l < 4; l++) s_[mt][nt][l] = 0.0f;

#pragma unroll
        for (int ks = 0; ks < 8; ks++) {
            uint32_t a[2][4];
#pragma unroll
            for (int mt = 0; mt < 2; mt++) {
                const float* Ar = sQw + (mt * 16 + g) * PSTR + ks * 8;
                a[mt][0] = __float_as_uint(Ar[t]);
                a[mt][1] = __float_as_uint(Ar[8 * PSTR + t]);
                a[mt][2] = __float_as_uint(Ar[t + 4]);
                a[mt][3] = __float_as_uint(Ar[8 * PSTR + t + 4]);
            }
#pragma unroll
            for (int nt = 0; nt < 8; nt++) {
                const float* Kr = sK + (nt * 8 + g) * KSTR + ks * 8;
                uint32_t b0 = __float_as_uint(Kr[t]);
                uint32_t b1 = __float_as_uint(Kr[t + 4]);
                mma_tf32(s_[0][nt], a[0][0], a[0][1], a[0][2], a[0][3], b0, b1);
                mma_tf32(s_[1][nt], a[1][0], a[1][1], a[1][2], a[1][3], b0, b1);
            }
        }

        // ---- online softmax per m-tile
#pragma unroll
        for (int mt = 0; mt < 2; mt++) {
            float mx0 = -1e30f, mx1 = -1e30f;
#pragma unroll
            for (int nt = 0; nt < 8; nt++) {
                mx0 = fmaxf(mx0, fmaxf(s_[mt][nt][0], s_[mt][nt][1]));
                mx1 = fmaxf(mx1, fmaxf(s_[mt][nt][2], s_[mt][nt][3]));
            }
            mx0 = fmaxf(mx0, __shfl_xor_sync(0xffffffffu, mx0, 1));
            mx0 = fmaxf(mx0, __shfl_xor_sync(0xffffffffu, mx0, 2));
            mx1 = fmaxf(mx1, __shfl_xor_sync(0xffffffffu, mx1, 1));
            mx1 = fmaxf(mx1, __shfl_xor_sync(0xffffffffu, mx1, 2));

            float mn0 = fmaxf(mrow[mt][0], mx0), mn1 = fmaxf(mrow[mt][1], mx1);
            float al0 = __expf(mrow[mt][0] - mn0), al1 = __expf(mrow[mt][1] - mn1);
            mrow[mt][0] = mn0; mrow[mt][1] = mn1;

            float s0 = 0.0f, s1 = 0.0f;
#pragma unroll
            for (int nt = 0; nt < 8; nt++) {
                s_[mt][nt][0] = __expf(s_[mt][nt][0] - mn0); s0 += s_[mt][nt][0];
                s_[mt][nt][1] = __expf(s_[mt][nt][1] - mn0); s0 += s_[mt][nt][1];
                s_[mt][nt][2] = __expf(s_[mt][nt][2] - mn1); s1 += s_[mt][nt][2];
                s_[mt][nt][3] = __expf(s_[mt][nt][3] - mn1); s1 += s_[mt][nt][3];
            }
            s0 += __shfl_xor_sync(0xffffffffu, s0, 1);
            s0 += __shfl_xor_sync(0xffffffffu, s0, 2);
            s1 += __shfl_xor_sync(0xffffffffu, s1, 1);
            s1 += __shfl_xor_sync(0xffffffffu, s1, 2);
            lrow[mt][0] = lrow[mt][0] * al0 + s0;
            lrow[mt][1] = lrow[mt][1] * al1 + s1;

#pragma unroll
            for (int nt = 0; nt < 8; nt++) {
                o_[mt][nt][0] *= al0; o_[mt][nt][1] *= al0;
                o_[mt][nt][2] *= al1; o_[mt][nt][3] *= al1;
            }

            // stage P (tf32-rounded) D-layout -> A-layout
#pragma unroll
            for (int nt = 0; nt < 8; nt++) {
                float2 p01 = make_float2(round_tf32(s_[mt][nt][0]), round_tf32(s_[mt][nt][1]));
                float2 p23 = make_float2(round_tf32(s_[mt][nt][2]), round_tf32(s_[mt][nt][3]));
                *(float2*)&sPw[(mt * 16 + g) * PSTR + nt * 8 + 2 * t]     = p01;
                *(float2*)&sPw[(mt * 16 + g + 8) * PSTR + nt * 8 + 2 * t] = p23;
            }
        }
        __syncwarp();

        // ---- O += P V   (32 x 64 per warp; V frags reused x2)
#pragma unroll
        for (int kt = 0; kt < 8; kt++) {
            uint32_t a[2][4];
#pragma unroll
            for (int mt = 0; mt < 2; mt++) {
                const float* Pr = sPw + (mt * 16 + g) * PSTR + kt * 8;
                a[mt][0] = __float_as_uint(Pr[t]);
                a[mt][1] = __float_as_uint(Pr[8 * PSTR + t]);
                a[mt][2] = __float_as_uint(Pr[t + 4]);
                a[mt][3] = __float_as_uint(Pr[8 * PSTR + t + 4]);
            }
#pragma unroll
            for (int nt = 0; nt < 8; nt++) {
                const float* Vr = sV + (kt * 8 + t) * VSTR + nt * 8 + g;
                uint32_t b0 = __float_as_uint(Vr[0]);
                uint32_t b1 = __float_as_uint(Vr[4 * VSTR]);
                mma_tf32(o_[0][nt], a[0][0], a[0][1], a[0][2], a[0][3], b0, b1);
                mma_tf32(o_[1][nt], a[1][0], a[1][1], a[1][2], a[1][3], b0, b1);
            }
        }
        __syncwarp();
    }

    // ---- epilogue: normalize, round to tf32, write (B,S,D)
#pragma unroll
    for (int mt = 0; mt < 2; mt++) {
        const float inv0 = 1.0f / lrow[mt][0], inv1 = 1.0f / lrow[mt][1];
        const int row0 = qb * 256 + wid * 32 + mt * 16 + g;
#pragma unroll
        for (int nt = 0; nt < 8; nt++) {
            const int col = h * DK + nt * 8 + 2 * t;
            float2 v0, v1;
            v0.x = round_tf32(o_[mt][nt][0] * inv0); v0.y = round_tf32(o_[mt][nt][1] * inv0);
            v1.x = round_tf32(o_[mt][nt][2] * inv1); v1.y = round_tf32(o_[mt][nt][3] * inv1);
            *(float2*)&Oatt[((size_t)b * S_LEN + row0) * DMODEL + col]     = v0;
            *(float2*)&Oatt[((size_t)b * S_LEN + row0 + 8) * DMODEL + col] = v1;
        }
    }
}

// ---------------------------------------------------------------------------
extern "C" void kernel_launch(void* const* d_in, const int* in_sizes, int n_in,
                              void* d_out, int out_size)
{
    const float* x  = (const float*)d_in[0];
    const float* Wq = (const float*)d_in[1];
    const float* Wk = (const float*)d_in[2];
    const float* Wv = (const float*)d_in[3];
    const float* Wo = (const float*)d_in[4];
    float* out = (float*)d_out;

    float *qp, *kp, *vp, *attp, *rp;
    cudaGetSymbolAddress((void**)&qp,   g_q);
    cudaGetSymbolAddress((void**)&kp,   g_k);
    cudaGetSymbolAddress((void**)&vp,   g_v);
    cudaGetSymbolAddress((void**)&attp, g_att);
    cudaGetSymbolAddress((void**)&rp,   g_round);

    float* xr  = rp;
    float* wqr = rp + 4 * 1024 * 1024;
    float* wkr = rp + 5 * 1024 * 1024;
    float* wvr = rp + 6 * 1024 * 1024;
    float* wor = rp + 7 * 1024 * 1024;

    // 0) single fused tf32 rna pre-rounding of all GEMM inputs
    round_all_kernel<<<8192, 256>>>(x, Wq, Wk, Wv, Wo, xr, wqr, wkr, wvr, wor);

    cudaFuncSetAttribute(gemm_tc_kernel, cudaFuncAttributeMaxDynamicSharedMemorySize,
                         GEMM_SMEM);
    cudaFuncSetAttribute(attn_kernel, cudaFuncAttributeMaxDynamicSharedMemorySize,
                         ATTN_SMEM);

    // 1) Fused QKV projections (tf32 mma), scatter+round to (B,H,S,dk)
    dim3 gQKV(DMODEL / 128, M_TOTAL / 128, 3);
    gemm_tc_kernel<<<gQKV, 256, GEMM_SMEM>>>(xr, wqr, wkr, wvr, qp, kp, vp, 1);

    // 2) Flash attention (tf32 mma) -> (B,S,D), rounded
    dim3 gA(S_LEN / 256, BATCH * NHEADS);
    attn_kernel<<<gA, 256, ATTN_SMEM>>>(qp, kp, vp, attp);

    // 3) Output projection (tf32 mma) -> d_out
    dim3 gO(DMODEL / 128, M_TOTAL / 128, 1);
    gemm_tc_kernel<<<gO, 256, GEMM_SMEM>>>(attp, wor, wor, wor, out, out, out, 0);
}

// round 6
// speedup vs baseline: 4.6602x; 1.0119x over previous
#include <cuda_runtime.h>
#include <cstdint>

// Problem constants
#define S_LEN    2048
#define DMODEL   1024
#define NHEADS   16
#define DK       64
#define BATCH    2
#define M_TOTAL  (BATCH * S_LEN)   // 4096

// Scratch (allocation-free rule: __device__ globals)
__device__ float g_q[BATCH * NHEADS * S_LEN * DK];     // (B,H,S,dk) tf32-rounded
__device__ float g_k[BATCH * NHEADS * S_LEN * DK];
__device__ float g_v[BATCH * NHEADS * S_LEN * DK];
__device__ float g_att[BATCH * S_LEN * DMODEL];        // (B,S,D) tf32-rounded
__device__ float g_round[8 * 1024 * 1024];             // rounded x + 4 weights

// ---------------------------------------------------------------------------
// Helpers
// ---------------------------------------------------------------------------
__device__ __forceinline__ uint32_t smem_u32(const void* p) {
    uint32_t a;
    asm("{ .reg .u64 t; cvta.to.shared.u64 t, %1; cvt.u32.u64 %0, t; }"
        : "=r"(a) : "l"(p));
    return a;
}

__device__ __forceinline__ void cp_async16(uint32_t s, const void* g) {
    asm volatile("cp.async.cg.shared.global [%0], [%1], 16;" :: "r"(s), "l"(g));
}
#define CP_COMMIT() asm volatile("cp.async.commit_group;" ::: "memory")
#define CP_WAIT(n)  asm volatile("cp.async.wait_group %0;" :: "n"(n) : "memory")

__device__ __forceinline__ float round_tf32(float v) {
    uint32_t u;
    asm("cvt.rna.tf32.f32 %0, %1;" : "=r"(u) : "f"(v));
    return __uint_as_float(u);
}

// D(16x8) += A(16x8,row) * B(8x8,col)  -- tf32, fp32 accum
__device__ __forceinline__ void mma_tf32(float* d,
                                         uint32_t a0, uint32_t a1, uint32_t a2, uint32_t a3,
                                         uint32_t b0, uint32_t b1) {
    asm volatile(
        "mma.sync.aligned.m16n8k8.row.col.f32.tf32.tf32.f32 "
        "{%0,%1,%2,%3}, {%4,%5,%6,%7}, {%8,%9}, {%0,%1,%2,%3};"
        : "+f"(d[0]), "+f"(d[1]), "+f"(d[2]), "+f"(d[3])
        : "r"(a0), "r"(a1), "r"(a2), "r"(a3), "r"(b0), "r"(b1));
}

// ---------------------------------------------------------------------------
// Single fused tf32 rounding pass over x + 4 weights.
// ---------------------------------------------------------------------------
__global__ __launch_bounds__(256) void round_all_kernel(
    const float* __restrict__ x,
    const float* __restrict__ wq, const float* __restrict__ wk,
    const float* __restrict__ wv, const float* __restrict__ wo,
    float* __restrict__ xr,
    float* __restrict__ wqr, float* __restrict__ wkr,
    float* __restrict__ wvr, float* __restrict__ wor)
{
    const int bidx = blockIdx.x;
    const float* src;
    float* dst;
    int off;
    if (bidx < 4096) { src = x; dst = xr; off = bidx; }
    else {
        const int i = (bidx - 4096) >> 10;
        off = (bidx - 4096) & 1023;
        src = (i == 0) ? wq : (i == 1) ? wk : (i == 2) ? wv : wo;
        dst = (i == 0) ? wqr : (i == 1) ? wkr : (i == 2) ? wvr : wor;
    }
    const int idx = off * 256 + threadIdx.x;
    float4 v = ((const float4*)src)[idx];
    float4 o;
    o.x = round_tf32(v.x); o.y = round_tf32(v.y);
    o.z = round_tf32(v.z); o.w = round_tf32(v.w);
    ((float4*)dst)[idx] = o;
}

// ---------------------------------------------------------------------------
// tf32 mma.sync GEMM: C[m][n] = sum_k A[m][k]*W[n][k]. M=4096,N=1024,K=1024.
// CTA: 256 thr (8 warps), tile 128x128, warp = 32m x 64n.
// K chunk = 32 (128B row). XOR-swizzled smem (no pad): element (r, c4-group)
// stored at c4 ^ (r & 7). 3 stages x 32KB = 96KB -> 2 CTAs/SM AND prefetch
// distance 2. Fragment LDS proven conflict-free: banks (c4^g)*4 + t distinct.
// Inputs must be tf32-pre-rounded. scatter=1 -> (B,H,S,dk) + tf32-round.
// ---------------------------------------------------------------------------
#define CHUNKF  (128 * 32)               // floats per tile-stage (A or B), 16KB
#define GSTAGES 3
#define GEMM_SMEM (GSTAGES * 2 * CHUNKF * (int)sizeof(float))   // 98304

// pointer to swizzled 4-float group (row r, group c4) within a tile
__device__ __forceinline__ const float* swz(const float* base, int r, int c4) {
    return base + r * 32 + (((c4 ^ (r & 7)) & 7) << 2);
}

__global__ __launch_bounds__(256, 2) void gemm_tc_kernel(
    const float* __restrict__ A,
    const float* __restrict__ W0, const float* __restrict__ W1, const float* __restrict__ W2,
    float* __restrict__ C0, float* __restrict__ C1, float* __restrict__ C2,
    int scatter)
{
    const float* __restrict__ W = (blockIdx.z == 0) ? W0 : (blockIdx.z == 1) ? W1 : W2;
    float* __restrict__ C       = (blockIdx.z == 0) ? C0 : (blockIdx.z == 1) ? C1 : C2;

    extern __shared__ float sm[];

    const int tid  = threadIdx.x;
    const int wid  = tid >> 5;
    const int lane = tid & 31;
    const int g    = lane >> 2;          // 0..7 row group
    const int t    = lane & 3;           // 0..3 thread-in-group
    const int wm   = wid & 3;            // warp m index (32 rows each)
    const int wn   = wid >> 2;           // warp n index (64 cols each)
    const int nBase = blockIdx.x * 128;
    const int mBase = blockIdx.y * 128;

    const int ldRow  = tid >> 1;         // 0..127
    const int ldHalf = tid & 1;          // 0/1 -> cols [0..15] or [16..31]
    const float* Ag = A + (size_t)(mBase + ldRow) * DMODEL + ldHalf * 16;
    const float* Wg = W + (size_t)(nBase + ldRow) * DMODEL + ldHalf * 16;

    float acc[2][8][4];
#pragma unroll
    for (int i = 0; i < 2; i++)
#pragma unroll
        for (int j = 0; j < 8; j++)
#pragma unroll
            for (int l = 0; l < 4; l++) acc[i][j][l] = 0.0f;

    const uint32_t smemA0 = smem_u32(sm);

    // issue loads for chunk c into stage s (swizzled 16B groups)
    auto issue = [&](int c, int s) {
        const float* aS = Ag + c * 32;
        const float* bS = Wg + c * 32;
        const uint32_t stageOff = (uint32_t)(s * 2 * CHUNKF) * 4u;
#pragma unroll
        for (int i = 0; i < 4; i++) {
            const int c4 = ldHalf * 4 + i;
            const uint32_t off =
                (uint32_t)(ldRow * 32 + (((c4 ^ (ldRow & 7)) & 7) << 2)) * 4u;
            cp_async16(smemA0 + stageOff + off, aS + i * 4);
            cp_async16(smemA0 + stageOff + (uint32_t)CHUNKF * 4u + off, bS + i * 4);
        }
    };

    issue(0, 0); CP_COMMIT();
    issue(1, 1); CP_COMMIT();

    const int NCHUNK = DMODEL / 32;   // 32
    for (int c = 0; c < NCHUNK; c++) {
        CP_WAIT(1);           // chunk c resident (c+1 may still be in flight)
        __syncthreads();
        if (c + 2 < NCHUNK) issue(c + 2, (c + 2) % GSTAGES);
        CP_COMMIT();          // empty group in tail keeps accounting exact

        const float* As = sm + (c % GSTAGES) * 2 * CHUNKF;
        const float* Bs = As + CHUNKF;

#pragma unroll
        for (int ks = 0; ks < 4; ks++) {
            const int c4a = 2 * ks, c4b = 2 * ks + 1;
            uint32_t a[2][4];
#pragma unroll
            for (int mt = 0; mt < 2; mt++) {
                const int row = wm * 32 + mt * 16 + g;
                a[mt][0] = __float_as_uint(swz(As, row,     c4a)[t]);
                a[mt][1] = __float_as_uint(swz(As, row + 8, c4a)[t]);
                a[mt][2] = __float_as_uint(swz(As, row,     c4b)[t]);
                a[mt][3] = __float_as_uint(swz(As, row + 8, c4b)[t]);
            }
#pragma unroll
            for (int nt = 0; nt < 8; nt++) {
                const int rowb = wn * 64 + nt * 8 + g;
                uint32_t b0 = __float_as_uint(swz(Bs, rowb, c4a)[t]);
                uint32_t b1 = __float_as_uint(swz(Bs, rowb, c4b)[t]);
                mma_tf32(acc[0][nt], a[0][0], a[0][1], a[0][2], a[0][3], b0, b1);
                mma_tf32(acc[1][nt], a[1][0], a[1][1], a[1][2], a[1][3], b0, b1);
            }
        }
    }

    // Epilogue: c0,c1 -> row r, cols 2t,2t+1 ; c2,c3 -> row r+8
#pragma unroll
    for (int mt = 0; mt < 2; mt++) {
#pragma unroll
        for (int half = 0; half < 2; half++) {
            const int m = mBase + wm * 32 + mt * 16 + g + half * 8;
#pragma unroll
            for (int nt = 0; nt < 8; nt++) {
                const int n = nBase + wn * 64 + nt * 8 + 2 * t;
                float2 v;
                v.x = acc[mt][nt][half * 2 + 0];
                v.y = acc[mt][nt][half * 2 + 1];
                if (scatter) {
                    v.x = round_tf32(v.x); v.y = round_tf32(v.y);
                    const int b = m >> 11, s = m & 2047;
                    const int head = n >> 6, d0 = n & 63;
                    *(float2*)&C[(((size_t)((b << 4) + head) * S_LEN + s) * DK + d0)] = v;
                } else {
                    *(float2*)&C[(size_t)m * DMODEL + n] = v;
                }
            }
        }
    }
}

// ---------------------------------------------------------------------------
// Flash attention with tf32 mma.sync (unchanged).
// CTA: 256 thr (8 warps). Q block = 256 rows (32 rows = 2 m-tiles per warp).
// ---------------------------------------------------------------------------
#define KSTR 68          // sK row stride (floats)
#define VSTR 72          // sV row stride
#define PSTR 68          // sP/sQ row stride
#define SK_F   (64 * KSTR)             // 4352
#define SV_F   (64 * VSTR)             // 4608
#define STAGE_F (SK_F + SV_F)          // 8960
#define SP_OFF (2 * STAGE_F)           // 17920
#define SQ_OFF (SP_OFF + 8 * 32 * PSTR)
#define ATTN_F (SQ_OFF + 8 * 32 * PSTR)
#define ATTN_SMEM (ATTN_F * (int)sizeof(float))   // 210944 bytes

__global__ __launch_bounds__(256) void attn_kernel(
    const float* __restrict__ Q, const float* __restrict__ K,
    const float* __restrict__ V, float* __restrict__ Oatt)
{
    extern __shared__ float sm[];

    const int tid  = threadIdx.x;
    const int wid  = tid >> 5;
    const int lane = tid & 31;
    const int g    = lane >> 2;
    const int t    = lane & 3;
    const int qb   = blockIdx.x;            // 0..7  (256 rows each)
    const int bh   = blockIdx.y;            // 0..31
    const int b    = bh >> 4;
    const int h    = bh & 15;

    float* sPw = sm + SP_OFF + wid * 32 * PSTR;
    float* sQw = sm + SQ_OFF + wid * 32 * PSTR;

    // ---- Stage Q slice (32 rows per warp), pre-scaled by 1/sqrt(dk)=0.125
    {
        const float* Qg = Q + ((size_t)bh * S_LEN + qb * 256 + wid * 32) * DK;
#pragma unroll
        for (int i = 0; i < 16; i++) {
            int idx = lane + 32 * i;
            int r = idx >> 4, c = idx & 15;
            float4 v = *(const float4*)&Qg[r * DK + c * 4];
            v.x *= 0.125f; v.y *= 0.125f; v.z *= 0.125f; v.w *= 0.125f;
            *(float4*)&sQw[r * PSTR + c * 4] = v;
        }
        __syncwarp();
    }

    float o_[2][8][4];
#pragma unroll
    for (int mt = 0; mt < 2; mt++)
#pragma unroll
        for (int nt = 0; nt < 8; nt++)
#pragma unroll
            for (int l = 0; l < 4; l++) o_[mt][nt][l] = 0.0f;
    float mrow[2][2] = {{-1e30f, -1e30f}, {-1e30f, -1e30f}};
    float lrow[2][2] = {{0.0f, 0.0f}, {0.0f, 0.0f}};

    const float* Kg = K + (size_t)bh * S_LEN * DK;
    const float* Vg = V + (size_t)bh * S_LEN * DK;
    const uint32_t smemB = smem_u32(sm);

    auto issue = [&](int kv, int st) {
        uint32_t dK = smemB + (uint32_t)(st * STAGE_F) * 4u;
        uint32_t dV = dK + (uint32_t)SK_F * 4u;
        const float* kS = Kg + (size_t)kv * 64 * DK;
        const float* vS = Vg + (size_t)kv * 64 * DK;
#pragma unroll
        for (int i = 0; i < 4; i++) {
            int q4 = tid + 256 * i;
            int r = q4 >> 4, qc = q4 & 15;
            cp_async16(dK + (uint32_t)(r * KSTR + qc * 4) * 4u, kS + r * DK + qc * 4);
            cp_async16(dV + (uint32_t)(r * VSTR + qc * 4) * 4u, vS + r * DK + qc * 4);
        }
    };

    issue(0, 0); CP_COMMIT();

    const int NKV = S_LEN / 64;   // 32
    for (int kv = 0; kv < NKV; kv++) {
        CP_WAIT(0);
        __syncthreads();
        if (kv + 1 < NKV) issue(kv + 1, (kv + 1) & 1);
        CP_COMMIT();

        const float* sK = sm + (kv & 1) * STAGE_F;
        const float* sV = sK + SK_F;

        // ---- scores S = (Q/8) K^T   (32 x 64 per warp; K frags reused x2)
        float s_[2][8][4];
#pragma unroll
        for (int mt = 0; mt < 2; mt++)
#pragma unroll
            for (int nt = 0; nt < 8; nt++)
#pragma unroll
                for (int l = 0; l < 4; l++) s_[mt][nt][l] = 0.0f;

#pragma unroll
        for (int ks = 0; ks < 8; ks++) {
            uint32_t a[2][4];
#pragma unroll
            for (int mt = 0; mt < 2; mt++) {
                const float* Ar = sQw + (mt * 16 + g) * PSTR + ks * 8;
                a[mt][0] = __float_as_uint(Ar[t]);
                a[mt][1] = __float_as_uint(Ar[8 * PSTR + t]);
                a[mt][2] = __float_as_uint(Ar[t + 4]);
                a[mt][3] = __float_as_uint(Ar[8 * PSTR + t + 4]);
            }
#pragma unroll
            for (int nt = 0; nt < 8; nt++) {
                const float* Kr = sK + (nt * 8 + g) * KSTR + ks * 8;
                uint32_t b0 = __float_as_uint(Kr[t]);
                uint32_t b1 = __float_as_uint(Kr[t + 4]);
                mma_tf32(s_[0][nt], a[0][0], a[0][1], a[0][2], a[0][3], b0, b1);
                mma_tf32(s_[1][nt], a[1][0], a[1][1], a[1][2], a[1][3], b0, b1);
            }
        }

        // ---- online softmax per m-tile
#pragma unroll
        for (int mt = 0; mt < 2; mt++) {
            float mx0 = -1e30f, mx1 = -1e30f;
#pragma unroll
            for (int nt = 0; nt < 8; nt++) {
                mx0 = fmaxf(mx0, fmaxf(s_[mt][nt][0], s_[mt][nt][1]));
                mx1 = fmaxf(mx1, fmaxf(s_[mt][nt][2], s_[mt][nt][3]));
            }
            mx0 = fmaxf(mx0, __shfl_xor_sync(0xffffffffu, mx0, 1));
            mx0 = fmaxf(mx0, __shfl_xor_sync(0xffffffffu, mx0, 2));
            mx1 = fmaxf(mx1, __shfl_xor_sync(0xffffffffu, mx1, 1));
            mx1 = fmaxf(mx1, __shfl_xor_sync(0xffffffffu, mx1, 2));

            float mn0 = fmaxf(mrow[mt][0], mx0), mn1 = fmaxf(mrow[mt][1], mx1);
            float al0 = __expf(mrow[mt][0] - mn0), al1 = __expf(mrow[mt][1] - mn1);
            mrow[mt][0] = mn0; mrow[mt][1] = mn1;

            float s0 = 0.0f, s1 = 0.0f;
#pragma unroll
            for (int nt = 0; nt < 8; nt++) {
                s_[mt][nt][0] = __expf(s_[mt][nt][0] - mn0); s0 += s_[mt][nt][0];
                s_[mt][nt][1] = __expf(s_[mt][nt][1] - mn0); s0 += s_[mt][nt][1];
                s_[mt][nt][2] = __expf(s_[mt][nt][2] - mn1); s1 += s_[mt][nt][2];
                s_[mt][nt][3] = __expf(s_[mt][nt][3] - mn1); s1 += s_[mt][nt][3];
            }
            s0 += __shfl_xor_sync(0xffffffffu, s0, 1);
            s0 += __shfl_xor_sync(0xffffffffu, s0, 2);
            s1 += __shfl_xor_sync(0xffffffffu, s1, 1);
            s1 += __shfl_xor_sync(0xffffffffu, s1, 2);
            lrow[mt][0] = lrow[mt][0] * al0 + s0;
            lrow[mt][1] = lrow[mt][1] * al1 + s1;

#pragma unroll
            for (int nt = 0; nt < 8; nt++) {
                o_[mt][nt][0] *= al0; o_[mt][nt][1] *= al0;
                o_[mt][nt][2] *= al1; o_[mt][nt][3] *= al1;
            }

            // stage P (tf32-rounded) D-layout -> A-layout
#pragma unroll
            for (int nt = 0; nt < 8; nt++) {
                float2 p01 = make_float2(round_tf32(s_[mt][nt][0]), round_tf32(s_[mt][nt][1]));
                float2 p23 = make_float2(round_tf32(s_[mt][nt][2]), round_tf32(s_[mt][nt][3]));
                *(float2*)&sPw[(mt * 16 + g) * PSTR + nt * 8 + 2 * t]     = p01;
                *(float2*)&sPw[(mt * 16 + g + 8) * PSTR + nt * 8 + 2 * t] = p23;
            }
        }
        __syncwarp();

        // ---- O += P V   (32 x 64 per warp; V frags reused x2)
#pragma unroll
        for (int kt = 0; kt < 8; kt++) {
            uint32_t a[2][4];
#pragma unroll
            for (int mt = 0; mt < 2; mt++) {
                const float* Pr = sPw + (mt * 16 + g) * PSTR + kt * 8;
                a[mt][0] = __float_as_uint(Pr[t]);
                a[mt][1] = __float_as_uint(Pr[8 * PSTR + t]);
                a[mt][2] = __float_as_uint(Pr[t + 4]);
                a[mt][3] = __float_as_uint(Pr[8 * PSTR + t + 4]);
            }
#pragma unroll
            for (int nt = 0; nt < 8; nt++) {
                const float* Vr = sV + (kt * 8 + t) * VSTR + nt * 8 + g;
                uint32_t b0 = __float_as_uint(Vr[0]);
                uint32_t b1 = __float_as_uint(Vr[4 * VSTR]);
                mma_tf32(o_[0][nt], a[0][0], a[0][1], a[0][2], a[0][3], b0, b1);
                mma_tf32(o_[1][nt], a[1][0], a[1][1], a[1][2], a[1][3], b0, b1);
            }
        }
        __syncwarp();
    }

    // ---- epilogue: normalize, round to tf32, write (B,S,D)
#pragma unroll
    for (int mt = 0; mt < 2; mt++) {
        const float inv0 = 1.0f / lrow[mt][0], inv1 = 1.0f / lrow[mt][1];
        const int row0 = qb * 256 + wid * 32 + mt * 16 + g;
#pragma unroll
        for (int nt = 0; nt < 8; nt++) {
            const int col = h * DK + nt * 8 + 2 * t;
            float2 v0, v1;
            v0.x = round_tf32(o_[mt][nt][0] * inv0); v0.y = round_tf32(o_[mt][nt][1] * inv0);
            v1.x = round_tf32(o_[mt][nt][2] * inv1); v1.y = round_tf32(o_[mt][nt][3] * inv1);
            *(float2*)&Oatt[((size_t)b * S_LEN + row0) * DMODEL + col]     = v0;
            *(float2*)&Oatt[((size_t)b * S_LEN + row0 + 8) * DMODEL + col] = v1;
        }
    }
}

// ---------------------------------------------------------------------------
extern "C" void kernel_launch(void* const* d_in, const int* in_sizes, int n_in,
                              void* d_out, int out_size)
{
    const float* x  = (const float*)d_in[0];
    const float* Wq = (const float*)d_in[1];
    const float* Wk = (const float*)d_in[2];
    const float* Wv = (const float*)d_in[3];
    const float* Wo = (const float*)d_in[4];
    float* out = (float*)d_out;

    float *qp, *kp, *vp, *attp, *rp;
    cudaGetSymbolAddress((void**)&qp,   g_q);
    cudaGetSymbolAddress((void**)&kp,   g_k);
    cudaGetSymbolAddress((void**)&vp,   g_v);
    cudaGetSymbolAddress((void**)&attp, g_att);
    cudaGetSymbolAddress((void**)&rp,   g_round);

    float* xr  = rp;
    float* wqr = rp + 4 * 1024 * 1024;
    float* wkr = rp + 5 * 1024 * 1024;
    float* wvr = rp + 6 * 1024 * 1024;
    float* wor = rp + 7 * 1024 * 1024;

    // 0) single fused tf32 rna pre-rounding of all GEMM inputs
    round_all_kernel<<<8192, 256>>>(x, Wq, Wk, Wv, Wo, xr, wqr, wkr, wvr, wor);

    cudaFuncSetAttribute(gemm_tc_kernel, cudaFuncAttributeMaxDynamicSharedMemorySize,
                         GEMM_SMEM);
    cudaFuncSetAttribute(attn_kernel, cudaFuncAttributeMaxDynamicSharedMemorySize,
                         ATTN_SMEM);

    // 1) Fused QKV projections (tf32 mma), scatter+round to (B,H,S,dk)
    dim3 gQKV(DMODEL / 128, M_TOTAL / 128, 3);
    gemm_tc_kernel<<<gQKV, 256, GEMM_SMEM>>>(xr, wqr, wkr, wvr, qp, kp, vp, 1);

    // 2) Flash attention (tf32 mma) -> (B,S,D), rounded
    dim3 gA(S_LEN / 256, BATCH * NHEADS);
    attn_kernel<<<gA, 256, ATTN_SMEM>>>(qp, kp, vp, attp);

    // 3) Output projection (tf32 mma) -> d_out
    dim3 gO(DMODEL / 128, M_TOTAL / 128, 1);
    gemm_tc_kernel<<<gO, 256, GEMM_SMEM>>>(attp, wor, wor, wor, out, out, out, 0);
}

// round 7
// speedup vs baseline: 6.1591x; 1.3216x over previous
#include <cuda_runtime.h>
#include <cstdint>

// Problem constants
#define S_LEN    2048
#define DMODEL   1024
#define NHEADS   16
#define DK       64
#define BATCH    2
#define M_TOTAL  (BATCH * S_LEN)   // 4096

// Scratch (allocation-free rule: __device__ globals)
__device__ float g_q[BATCH * NHEADS * S_LEN * DK];     // (B,H,S,dk) tf32-rounded
__device__ float g_k[BATCH * NHEADS * S_LEN * DK];
__device__ float g_v[BATCH * NHEADS * S_LEN * DK];
__device__ float g_att[BATCH * S_LEN * DMODEL];        // (B,S,D) tf32-rounded
__device__ float g_round[8 * 1024 * 1024];             // rounded x + 4 weights

// ---------------------------------------------------------------------------
// Helpers
// ---------------------------------------------------------------------------
__device__ __forceinline__ uint32_t smem_u32(const void* p) {
    uint32_t a;
    asm("{ .reg .u64 t; cvta.to.shared.u64 t, %1; cvt.u32.u64 %0, t; }"
        : "=r"(a) : "l"(p));
    return a;
}

__device__ __forceinline__ void cp_async16(uint32_t s, const void* g) {
    asm volatile("cp.async.cg.shared.global [%0], [%1], 16;" :: "r"(s), "l"(g));
}
#define CP_COMMIT() asm volatile("cp.async.commit_group;" ::: "memory")
#define CP_WAIT(n)  asm volatile("cp.async.wait_group %0;" :: "n"(n) : "memory")

__device__ __forceinline__ float round_tf32(float v) {
    uint32_t u;
    asm("cvt.rna.tf32.f32 %0, %1;" : "=r"(u) : "f"(v));
    return __uint_as_float(u);
}

// D(16x8) += A(16x8,row) * B(8x8,col)  -- tf32, fp32 accum
__device__ __forceinline__ void mma_tf32(float* d,
                                         uint32_t a0, uint32_t a1, uint32_t a2, uint32_t a3,
                                         uint32_t b0, uint32_t b1) {
    asm volatile(
        "mma.sync.aligned.m16n8k8.row.col.f32.tf32.tf32.f32 "
        "{%0,%1,%2,%3}, {%4,%5,%6,%7}, {%8,%9}, {%0,%1,%2,%3};"
        : "+f"(d[0]), "+f"(d[1]), "+f"(d[2]), "+f"(d[3])
        : "r"(a0), "r"(a1), "r"(a2), "r"(a3), "r"(b0), "r"(b1));
}

// ldmatrix x4: one instr loads four 8x8-b16 tiles (= four 8x4-f32 tiles)
__device__ __forceinline__ void ldsm4(uint32_t* r, uint32_t addr) {
    asm volatile("ldmatrix.sync.aligned.m8n8.x4.shared.b16 {%0,%1,%2,%3}, [%4];"
        : "=r"(r[0]), "=r"(r[1]), "=r"(r[2]), "=r"(r[3]) : "r"(addr));
}

// ---------------------------------------------------------------------------
// Single fused tf32 rounding pass over x + 4 weights.
// ---------------------------------------------------------------------------
__global__ __launch_bounds__(256) void round_all_kernel(
    const float* __restrict__ x,
    const float* __restrict__ wq, const float* __restrict__ wk,
    const float* __restrict__ wv, const float* __restrict__ wo,
    float* __restrict__ xr,
    float* __restrict__ wqr, float* __restrict__ wkr,
    float* __restrict__ wvr, float* __restrict__ wor)
{
    const int bidx = blockIdx.x;
    const float* src;
    float* dst;
    int off;
    if (bidx < 4096) { src = x; dst = xr; off = bidx; }
    else {
        const int i = (bidx - 4096) >> 10;
        off = (bidx - 4096) & 1023;
        src = (i == 0) ? wq : (i == 1) ? wk : (i == 2) ? wv : wo;
        dst = (i == 0) ? wqr : (i == 1) ? wkr : (i == 2) ? wvr : wor;
    }
    const int idx = off * 256 + threadIdx.x;
    float4 v = ((const float4*)src)[idx];
    float4 o;
    o.x = round_tf32(v.x); o.y = round_tf32(v.y);
    o.z = round_tf32(v.z); o.w = round_tf32(v.w);
    ((float4*)dst)[idx] = o;
}

// ---------------------------------------------------------------------------
// tf32 mma.sync GEMM: C[m][n] = sum_k A[m][k]*W[n][k]. M=4096,N=1024,K=1024.
// CTA: 256 thr (8 warps), tile 256x128, warp = 64m x 64n (4 m-warps x 2 n-warps).
// K chunk = 32 (128B row), XOR-swizzled smem, 3 stages (48KB each) = 144KB,
// prefetch distance 2. Fragments loaded via ldmatrix.x4 (conflict-free).
// Inputs must be tf32-pre-rounded. scatter=1 -> (B,H,S,dk) + tf32-round.
// ---------------------------------------------------------------------------
#define GTM 256
#define GTN 128
#define A_STAGE_F (GTM * 32)                 // 8192 floats = 32KB
#define B_STAGE_F (GTN * 32)                 // 4096 floats = 16KB
#define STG_F     (A_STAGE_F + B_STAGE_F)    // 12288 floats = 48KB
#define GSTAGES   3
#define GEMM_SMEM (GSTAGES * STG_F * (int)sizeof(float))   // 147456

__global__ __launch_bounds__(256, 1) void gemm_tc_kernel(
    const float* __restrict__ A,
    const float* __restrict__ W0, const float* __restrict__ W1, const float* __restrict__ W2,
    float* __restrict__ C0, float* __restrict__ C1, float* __restrict__ C2,
    int scatter)
{
    const float* __restrict__ W = (blockIdx.z == 0) ? W0 : (blockIdx.z == 1) ? W1 : W2;
    float* __restrict__ C       = (blockIdx.z == 0) ? C0 : (blockIdx.z == 1) ? C1 : C2;

    extern __shared__ float sm[];

    const int tid  = threadIdx.x;
    const int wid  = tid >> 5;
    const int lane = tid & 31;
    const int g    = lane >> 2;          // 0..7 row group
    const int t    = lane & 3;           // 0..3 thread-in-group
    const int wm   = wid & 3;            // warp m index (64 rows each)
    const int wn   = wid >> 2;           // warp n index (64 cols each)
    const int nBase = blockIdx.x * GTN;
    const int mBase = blockIdx.y * GTM;

    float acc[4][8][4];
#pragma unroll
    for (int i = 0; i < 4; i++)
#pragma unroll
        for (int j = 0; j < 8; j++)
#pragma unroll
            for (int l = 0; l < 4; l++) acc[i][j][l] = 0.0f;

    const uint32_t smemA0 = smem_u32(sm);

    // --- ldmatrix per-lane row indices (row & 7 == lane & 7 for all) ---
    const int rowA = wm * 64 + (lane & 15);                       // + mt*16
    const int rowB = wn * 64 + (lane & 7) + ((lane >> 4) << 3);   // + ntp*16
    const int c4bitA = lane >> 4;          // 0/1 -> k-group low/high
    const int c4bitB = (lane >> 3) & 1;
    const int lxor   = lane & 7;

    // issue loads for chunk c into stage s (swizzled 16B groups, coalesced)
    auto issue = [&](int c, int s) {
        const uint32_t st = smemA0 + (uint32_t)(s * STG_F) * 4u;
#pragma unroll
        for (int i = 0; i < 8; i++) {           // A: 2048 groups of 16B
            const int idx = tid + 256 * i;
            const int r = idx >> 3, c4 = idx & 7;
            const uint32_t off = (uint32_t)(r * 32 + (((c4 ^ (r & 7)) & 7) << 2)) * 4u;
            cp_async16(st + off, A + (size_t)(mBase + r) * DMODEL + c * 32 + c4 * 4);
        }
#pragma unroll
        for (int i = 0; i < 4; i++) {           // B: 1024 groups
            const int idx = tid + 256 * i;
            const int r = idx >> 3, c4 = idx & 7;
            const uint32_t off = (uint32_t)(r * 32 + (((c4 ^ (r & 7)) & 7) << 2)) * 4u;
            cp_async16(st + (uint32_t)A_STAGE_F * 4u + off,
                       W + (size_t)(nBase + r) * DMODEL + c * 32 + c4 * 4);
        }
    };

    issue(0, 0); CP_COMMIT();
    issue(1, 1); CP_COMMIT();

    const int NCHUNK = DMODEL / 32;   // 32
    for (int c = 0; c < NCHUNK; c++) {
        CP_WAIT(1);
        __syncthreads();
        if (c + 2 < NCHUNK) issue(c + 2, (c + 2) % GSTAGES);
        CP_COMMIT();

        const uint32_t Ast = smemA0 + (uint32_t)((c % GSTAGES) * STG_F) * 4u;
        const uint32_t Bst = Ast + (uint32_t)A_STAGE_F * 4u;

#pragma unroll
        for (int ks = 0; ks < 4; ks++) {
            const int xa = ((2 * ks + c4bitA) ^ lxor) & 7;
            const int xb = ((2 * ks + c4bitB) ^ lxor) & 7;

            uint32_t a[4][4];
#pragma unroll
            for (int mt = 0; mt < 4; mt++)
                ldsm4(a[mt], Ast + (uint32_t)((rowA + mt * 16) * 32 + xa * 4) * 4u);

            uint32_t b[4][4];
#pragma unroll
            for (int ntp = 0; ntp < 4; ntp++)
                ldsm4(b[ntp], Bst + (uint32_t)((rowB + ntp * 16) * 32 + xb * 4) * 4u);

#pragma unroll
            for (int mt = 0; mt < 4; mt++)
#pragma unroll
                for (int ntp = 0; ntp < 4; ntp++) {
                    mma_tf32(acc[mt][2 * ntp],     a[mt][0], a[mt][1], a[mt][2], a[mt][3],
                             b[ntp][0], b[ntp][1]);
                    mma_tf32(acc[mt][2 * ntp + 1], a[mt][0], a[mt][1], a[mt][2], a[mt][3],
                             b[ntp][2], b[ntp][3]);
                }
        }
    }

    // Epilogue: c0,c1 -> row r, cols 2t,2t+1 ; c2,c3 -> row r+8
#pragma unroll
    for (int mt = 0; mt < 4; mt++) {
#pragma unroll
        for (int half = 0; half < 2; half++) {
            const int m = mBase + wm * 64 + mt * 16 + g + half * 8;
#pragma unroll
            for (int nt = 0; nt < 8; nt++) {
                const int n = nBase + wn * 64 + nt * 8 + 2 * t;
                float2 v;
                v.x = acc[mt][nt][half * 2 + 0];
                v.y = acc[mt][nt][half * 2 + 1];
                if (scatter) {
                    v.x = round_tf32(v.x); v.y = round_tf32(v.y);
                    const int b = m >> 11, s = m & 2047;
                    const int head = n >> 6, d0 = n & 63;
                    *(float2*)&C[(((size_t)((b << 4) + head) * S_LEN + s) * DK + d0)] = v;
                } else {
                    *(float2*)&C[(size_t)m * DMODEL + n] = v;
                }
            }
        }
    }
}

// ---------------------------------------------------------------------------
// Flash attention with tf32 mma.sync (unchanged from round 6).
// CTA: 256 thr (8 warps). Q block = 256 rows (32 rows = 2 m-tiles per warp).
// ---------------------------------------------------------------------------
#define KSTR 68          // sK row stride (floats)
#define VSTR 72          // sV row stride
#define PSTR 68          // sP/sQ row stride
#define SK_F   (64 * KSTR)             // 4352
#define SV_F   (64 * VSTR)             // 4608
#define STAGE_F (SK_F + SV_F)          // 8960
#define SP_OFF (2 * STAGE_F)           // 17920
#define SQ_OFF (SP_OFF + 8 * 32 * PSTR)
#define ATTN_F (SQ_OFF + 8 * 32 * PSTR)
#define ATTN_SMEM (ATTN_F * (int)sizeof(float))   // 210944 bytes

__global__ __launch_bounds__(256) void attn_kernel(
    const float* __restrict__ Q, const float* __restrict__ K,
    const float* __restrict__ V, float* __restrict__ Oatt)
{
    extern __shared__ float sm[];

    const int tid  = threadIdx.x;
    const int wid  = tid >> 5;
    const int lane = tid & 31;
    const int g    = lane >> 2;
    const int t    = lane & 3;
    const int qb   = blockIdx.x;            // 0..7  (256 rows each)
    const int bh   = blockIdx.y;            // 0..31
    const int b    = bh >> 4;
    const int h    = bh & 15;

    float* sPw = sm + SP_OFF + wid * 32 * PSTR;
    float* sQw = sm + SQ_OFF + wid * 32 * PSTR;

    // ---- Stage Q slice (32 rows per warp), pre-scaled by 1/sqrt(dk)=0.125
    {
        const float* Qg = Q + ((size_t)bh * S_LEN + qb * 256 + wid * 32) * DK;
#pragma unroll
        for (int i = 0; i < 16; i++) {
            int idx = lane + 32 * i;
            int r = idx >> 4, c = idx & 15;
            float4 v = *(const float4*)&Qg[r * DK + c * 4];
            v.x *= 0.125f; v.y *= 0.125f; v.z *= 0.125f; v.w *= 0.125f;
            *(float4*)&sQw[r * PSTR + c * 4] = v;
        }
        __syncwarp();
    }

    float o_[2][8][4];
#pragma unroll
    for (int mt = 0; mt < 2; mt++)
#pragma unroll
        for (int nt = 0; nt < 8; nt++)
#pragma unroll
            for (int l = 0; l < 4; l++) o_[mt][nt][l] = 0.0f;
    float mrow[2][2] = {{-1e30f, -1e30f}, {-1e30f, -1e30f}};
    float lrow[2][2] = {{0.0f, 0.0f}, {0.0f, 0.0f}};

    const float* Kg = K + (size_t)bh * S_LEN * DK;
    const float* Vg = V + (size_t)bh * S_LEN * DK;
    const uint32_t smemB = smem_u32(sm);

    auto issue = [&](int kv, int st) {
        uint32_t dK = smemB + (uint32_t)(st * STAGE_F) * 4u;
        uint32_t dV = dK + (uint32_t)SK_F * 4u;
        const float* kS = Kg + (size_t)kv * 64 * DK;
        const float* vS = Vg + (size_t)kv * 64 * DK;
#pragma unroll
        for (int i = 0; i < 4; i++) {
            int q4 = tid + 256 * i;
            int r = q4 >> 4, qc = q4 & 15;
            cp_async16(dK + (uint32_t)(r * KSTR + qc * 4) * 4u, kS + r * DK + qc * 4);
            cp_async16(dV + (uint32_t)(r * VSTR + qc * 4) * 4u, vS + r * DK + qc * 4);
        }
    };

    issue(0, 0); CP_COMMIT();

    const int NKV = S_LEN / 64;   // 32
    for (int kv = 0; kv < NKV; kv++) {
        CP_WAIT(0);
        __syncthreads();
        if (kv + 1 < NKV) issue(kv + 1, (kv + 1) & 1);
        CP_COMMIT();

        const float* sK = sm + (kv & 1) * STAGE_F;
        const float* sV = sK + SK_F;

        // ---- scores S = (Q/8) K^T   (32 x 64 per warp; K frags reused x2)
        float s_[2][8][4];
#pragma unroll
        for (int mt = 0; mt < 2; mt++)
#pragma unroll
            for (int nt = 0; nt < 8; nt++)
#pragma unroll
                for (int l = 0; l < 4; l++) s_[mt][nt][l] = 0.0f;

#pragma unroll
        for (int ks = 0; ks < 8; ks++) {
            uint32_t a[2][4];
#pragma unroll
            for (int mt = 0; mt < 2; mt++) {
                const float* Ar = sQw + (mt * 16 + g) * PSTR + ks * 8;
                a[mt][0] = __float_as_uint(Ar[t]);
                a[mt][1] = __float_as_uint(Ar[8 * PSTR + t]);
                a[mt][2] = __float_as_uint(Ar[t + 4]);
                a[mt][3] = __float_as_uint(Ar[8 * PSTR + t + 4]);
            }
#pragma unroll
            for (int nt = 0; nt < 8; nt++) {
                const float* Kr = sK + (nt * 8 + g) * KSTR + ks * 8;
                uint32_t b0 = __float_as_uint(Kr[t]);
                uint32_t b1 = __float_as_uint(Kr[t + 4]);
                mma_tf32(s_[0][nt], a[0][0], a[0][1], a[0][2], a[0][3], b0, b1);
                mma_tf32(s_[1][nt], a[1][0], a[1][1], a[1][2], a[1][3], b0, b1);
            }
        }

        // ---- online softmax per m-tile
#pragma unroll
        for (int mt = 0; mt < 2; mt++) {
            float mx0 = -1e30f, mx1 = -1e30f;
#pragma unroll
            for (int nt = 0; nt < 8; nt++) {
                mx0 = fmaxf(mx0, fmaxf(s_[mt][nt][0], s_[mt][nt][1]));
                mx1 = fmaxf(mx1, fmaxf(s_[mt][nt][2], s_[mt][nt][3]));
            }
            mx0 = fmaxf(mx0, __shfl_xor_sync(0xffffffffu, mx0, 1));
            mx0 = fmaxf(mx0, __shfl_xor_sync(0xffffffffu, mx0, 2));
            mx1 = fmaxf(mx1, __shfl_xor_sync(0xffffffffu, mx1, 1));
            mx1 = fmaxf(mx1, __shfl_xor_sync(0xffffffffu, mx1, 2));

            float mn0 = fmaxf(mrow[mt][0], mx0), mn1 = fmaxf(mrow[mt][1], mx1);
            float al0 = __expf(mrow[mt][0] - mn0), al1 = __expf(mrow[mt][1] - mn1);
            mrow[mt][0] = mn0; mrow[mt][1] = mn1;

            float s0 = 0.0f, s1 = 0.0f;
#pragma unroll
            for (int nt = 0; nt < 8; nt++) {
                s_[mt][nt][0] = __expf(s_[mt][nt][0] - mn0); s0 += s_[mt][nt][0];
                s_[mt][nt][1] = __expf(s_[mt][nt][1] - mn0); s0 += s_[mt][nt][1];
                s_[mt][nt][2] = __expf(s_[mt][nt][2] - mn1); s1 += s_[mt][nt][2];
                s_[mt][nt][3] = __expf(s_[mt][nt][3] - mn1); s1 += s_[mt][nt][3];
            }
            s0 += __shfl_xor_sync(0xffffffffu, s0, 1);
            s0 += __shfl_xor_sync(0xffffffffu, s0, 2);
            s1 += __shfl_xor_sync(0xffffffffu, s1, 1);
            s1 += __shfl_xor_sync(0xffffffffu, s1, 2);
            lrow[mt][0] = lrow[mt][0] * al0 + s0;
            lrow[mt][1] = lrow[mt][1] * al1 + s1;

#pragma unroll
            for (int nt = 0; nt < 8; nt++) {
                o_[mt][nt][0] *= al0; o_[mt][nt][1] *= al0;
                o_[mt][nt][2] *= al1; o_[mt][nt][3] *= al1;
            }

            // stage P (tf32-rounded) D-layout -> A-layout
#pragma unroll
            for (int nt = 0; nt < 8; nt++) {
                float2 p01 = make_float2(round_tf32(s_[mt][nt][0]), round_tf32(s_[mt][nt][1]));
                float2 p23 = make_float2(round_tf32(s_[mt][nt][2]), round_tf32(s_[mt][nt][3]));
                *(float2*)&sPw[(mt * 16 + g) * PSTR + nt * 8 + 2 * t]     = p01;
                *(float2*)&sPw[(mt * 16 + g + 8) * PSTR + nt * 8 + 2 * t] = p23;
            }
        }
        __syncwarp();

        // ---- O += P V   (32 x 64 per warp; V frags reused x2)
#pragma unroll
        for (int kt = 0; kt < 8; kt++) {
            uint32_t a[2][4];
#pragma unroll
            for (int mt = 0; mt < 2; mt++) {
                const float* Pr = sPw + (mt * 16 + g) * PSTR + kt * 8;
                a[mt][0] = __float_as_uint(Pr[t]);
                a[mt][1] = __float_as_uint(Pr[8 * PSTR + t]);
                a[mt][2] = __float_as_uint(Pr[t + 4]);
                a[mt][3] = __float_as_uint(Pr[8 * PSTR + t + 4]);
            }
#pragma unroll
            for (int nt = 0; nt < 8; nt++) {
                const float* Vr = sV + (kt * 8 + t) * VSTR + nt * 8 + g;
                uint32_t b0 = __float_as_uint(Vr[0]);
                uint32_t b1 = __float_as_uint(Vr[4 * VSTR]);
                mma_tf32(o_[0][nt], a[0][0], a[0][1], a[0][2], a[0][3], b0, b1);
                mma_tf32(o_[1][nt], a[1][0], a[1][1], a[1][2], a[1][3], b0, b1);
            }
        }
        __syncwarp();
    }

    // ---- epilogue: normalize, round to tf32, write (B,S,D)
#pragma unroll
    for (int mt = 0; mt < 2; mt++) {
        const float inv0 = 1.0f / lrow[mt][0], inv1 = 1.0f / lrow[mt][1];
        const int row0 = qb * 256 + wid * 32 + mt * 16 + g;
#pragma unroll
        for (int nt = 0; nt < 8; nt++) {
            const int col = h * DK + nt * 8 + 2 * t;
            float2 v0, v1;
            v0.x = round_tf32(o_[mt][nt][0] * inv0); v0.y = round_tf32(o_[mt][nt][1] * inv0);
            v1.x = round_tf32(o_[mt][nt][2] * inv1); v1.y = round_tf32(o_[mt][nt][3] * inv1);
            *(float2*)&Oatt[((size_t)b * S_LEN + row0) * DMODEL + col]     = v0;
            *(float2*)&Oatt[((size_t)b * S_LEN + row0 + 8) * DMODEL + col] = v1;
        }
    }
}

// ---------------------------------------------------------------------------
extern "C" void kernel_launch(void* const* d_in, const int* in_sizes, int n_in,
                              void* d_out, int out_size)
{
    const float* x  = (const float*)d_in[0];
    const float* Wq = (const float*)d_in[1];
    const float* Wk = (const float*)d_in[2];
    const float* Wv = (const float*)d_in[3];
    const float* Wo = (const float*)d_in[4];
    float* out = (float*)d_out;

    float *qp, *kp, *vp, *attp, *rp;
    cudaGetSymbolAddress((void**)&qp,   g_q);
    cudaGetSymbolAddress((void**)&kp,   g_k);
    cudaGetSymbolAddress((void**)&vp,   g_v);
    cudaGetSymbolAddress((void**)&attp, g_att);
    cudaGetSymbolAddress((void**)&rp,   g_round);

    float* xr  = rp;
    float* wqr = rp + 4 * 1024 * 1024;
    float* wkr = rp + 5 * 1024 * 1024;
    float* wvr = rp + 6 * 1024 * 1024;
    float* wor = rp + 7 * 1024 * 1024;

    // 0) single fused tf32 rna pre-rounding of all GEMM inputs
    round_all_kernel<<<8192, 256>>>(x, Wq, Wk, Wv, Wo, xr, wqr, wkr, wvr, wor);

    cudaFuncSetAttribute(gemm_tc_kernel, cudaFuncAttributeMaxDynamicSharedMemorySize,
                         GEMM_SMEM);
    cudaFuncSetAttribute(attn_kernel, cudaFuncAttributeMaxDynamicSharedMemorySize,
                         ATTN_SMEM);

    // 1) Fused QKV projections (tf32 mma), scatter+round to (B,H,S,dk)
    dim3 gQKV(DMODEL / GTN, M_TOTAL / GTM, 3);
    gemm_tc_kernel<<<gQKV, 256, GEMM_SMEM>>>(xr, wqr, wkr, wvr, qp, kp, vp, 1);

    // 2) Flash attention (tf32 mma) -> (B,S,D), rounded
    dim3 gA(S_LEN / 256, BATCH * NHEADS);
    attn_kernel<<<gA, 256, ATTN_SMEM>>>(qp, kp, vp, attp);

    // 3) Output projection (tf32 mma) -> d_out
    dim3 gO(DMODEL / GTN, M_TOTAL / GTM, 1);
    gemm_tc_kernel<<<gO, 256, GEMM_SMEM>>>(attp, wor, wor, wor, out, out, out, 0);
}